// round 13
// baseline (speedup 1.0000x reference)
#include <cuda_runtime.h>

#define BB 64
#define NN 1024
#define KK 8     // 7 knn + self
#define F1 16
#define D1 64    // H1*C1 = 4*16
#define D2 128   // H2*C2 = 4*32

typedef unsigned long long ull;
typedef unsigned int u32;

// Scratch (allocation-free rule: __device__ globals)
__device__ float g_xl1[BB * NN * D1];
__device__ float g_xr1[BB * NN * D1];
__device__ float g_h1 [BB * NN * D1];
__device__ float g_xl2[BB * NN * D2];
__device__ float g_xr2[BB * NN * D2];
__device__ float g_part[BB * (NN / 8) * D2];   // attn2+pool partials (4MB)
__device__ int   g_idx[BB * NN * KK];

// Packed dual-fp32 ops (sm_103a f32x2 pipe — ptxas never emits from C++)
__device__ __forceinline__ ull fma2(ull a, ull b, ull c) {
    ull d;
    asm("fma.rn.f32x2 %0, %1, %2, %3;" : "=l"(d) : "l"(a), "l"(b), "l"(c));
    return d;
}
__device__ __forceinline__ ull add2(ull a, ull b) {
    ull d;
    asm("add.rn.f32x2 %0, %1, %2;" : "=l"(d) : "l"(a), "l"(b));
    return d;
}
__device__ __forceinline__ ull bcast2(float v) {
    ull d;
    asm("mov.b64 %0, {%1, %1};" : "=l"(d) : "r"(__float_as_uint(v)));
    return d;
}
__device__ __forceinline__ float lo32(ull v) { return __uint_as_float((u32)v); }
__device__ __forceinline__ float hi32(ull v) { return __uint_as_float((u32)(v >> 32)); }

// Quarter stride in floats: 128 pairs * 8 floats + 8 pad = 1032.
// Byte delta between quarters = 4128 -> bank shift 8 -> quarter q's LDS.128s
// occupy banks [8q,8q+3] and [8q+4,8q+7]: the 4 quarter-groups in a warp are
// conflict-free (this was the R12 bug: stride 4096 aliased all quarters to
// the same banks -> 4-way conflict on every scan load).
#define QSTRIDE 1032

// ---------------------------------------------------------------------------
// Stable merge of two sorted top-7 lists held by lane pairs (xor delta).
// Comparator (d,i): d strictly smaller wins; equal d -> smaller index wins.
// Register-shift two-pointer: no dynamic register indexing (no local mem).
// ---------------------------------------------------------------------------
__device__ __forceinline__ void merge7(float bd[7], int bi[7], int delta)
{
    float od[7]; int oi[7];
#pragma unroll
    for (int j = 0; j < 7; j++) {
        od[j] = __shfl_xor_sync(0xffffffffu, bd[j], delta);
        oi[j] = __shfl_xor_sync(0xffffffffu, bi[j], delta);
    }
    float rd[7]; int ri[7];
#pragma unroll
    for (int j = 0; j < 7; j++) {
        bool takeA = (bd[0] < od[0]) || (bd[0] == od[0] && bi[0] < oi[0]);
        rd[j] = takeA ? bd[0] : od[0];
        ri[j] = takeA ? bi[0] : oi[0];
#pragma unroll
        for (int k = 0; k < 6; k++) {
            bd[k] = takeA ? bd[k + 1] : bd[k];
            bi[k] = takeA ? bi[k + 1] : bi[k];
            od[k] = takeA ? od[k] : od[k + 1];
            oi[k] = takeA ? oi[k] : oi[k + 1];
        }
    }
#pragma unroll
    for (int j = 0; j < 7; j++) { bd[j] = rd[j]; bi[j] = ri[j]; }
}

// ---------------------------------------------------------------------------
// KNN, 4 threads per node with bank-skewed quarters: thread (node, q) scans
// candidates [q*256, (q+1)*256) stored pair-interleaved at spp + q*QSTRIDE
// (2 conflict-free LDS.128 + 4 f32x2 ops per 2 candidates), keeps a sorted
// top-7 (strict-< stable insert), then two shfl_xor merges produce the
// global top-7. Block = 256 threads = 64 nodes; grid = (16, 64 batches).
// ---------------------------------------------------------------------------
__global__ void knn_kernel(const float* __restrict__ pos)
{
    __shared__ __align__(16) float spp[4 * QSTRIDE];   // ~16.5KB
    int b = blockIdx.y;
    const float* p = pos + (size_t)b * NN * 3;
    for (int i = threadIdx.x; i < NN; i += blockDim.x) {
        float x = p[i * 3 + 0], y = p[i * 3 + 1], z = p[i * 3 + 2];
        float w = x * x + y * y + z * z;
        int pair = i >> 1;
        float* dst = spp + (pair >> 7) * QSTRIDE + (pair & 127) * 8 + (i & 1);
        dst[0] = x; dst[2] = y; dst[4] = z; dst[6] = w;
    }
    __syncthreads();

    int tid = threadIdx.x;
    int q   = tid & 3;                         // quarter 0..3
    int n   = blockIdx.x * 64 + (tid >> 2);    // node 0..1023
    const float* meq = spp + (n >> 8) * QSTRIDE + ((n >> 1) & 127) * 8 + (n & 1);
    float mex = meq[0], mey = meq[2], mez = meq[4], mew = meq[6];
    ull cx = bcast2(-2.f * mex), cy = bcast2(-2.f * mey),
        cz = bcast2(-2.f * mez), cw = bcast2(mew);

    float bd[7];
    int   bi[7];
#pragma unroll
    for (int j = 0; j < 7; j++) { bd[j] = 3.4028235e38f; bi[j] = 0; }

    const ulonglong2* pq = (const ulonglong2*)(spp + q * QSTRIDE);
    int mbase = q * 256;
#pragma unroll 1
    for (int j2 = 0; j2 < 128; j2++) {
        ulonglong2 a  = pq[2 * j2];      // {x0x1, y0y1}
        ulonglong2 c2 = pq[2 * j2 + 1];  // {z0z1, w0w1}
        ull d2 = add2(c2.y, cw);
        d2 = fma2(cx, a.x, d2);
        d2 = fma2(cy, a.y, d2);
        d2 = fma2(cz, c2.x, d2);
        float d0 = lo32(d2), d1 = hi32(d2);
        if (d0 < bd[6] || d1 < bd[6]) {
            int m0 = mbase + 2 * j2;
            if (d0 < bd[6] && m0 != n) {
                bd[6] = d0; bi[6] = m0;
#pragma unroll
                for (int j = 6; j > 0; j--) {
                    if (bd[j] < bd[j - 1]) {   // strict: ties keep earlier index
                        float td = bd[j]; bd[j] = bd[j - 1]; bd[j - 1] = td;
                        int   ti = bi[j]; bi[j] = bi[j - 1]; bi[j - 1] = ti;
                    }
                }
            }
            if (d1 < bd[6] && (m0 + 1) != n) {
                bd[6] = d1; bi[6] = m0 + 1;
#pragma unroll
                for (int j = 6; j > 0; j--) {
                    if (bd[j] < bd[j - 1]) {
                        float td = bd[j]; bd[j] = bd[j - 1]; bd[j - 1] = td;
                        int   ti = bi[j]; bi[j] = bi[j - 1]; bi[j - 1] = ti;
                    }
                }
            }
        }
    }

    // Merge the 4 quarter-lists (lanes 4k+{0,1,2,3}) into the global top-7.
    merge7(bd, bi, 1);
    merge7(bd, bi, 2);

    if (q == 0) {
        int* o = g_idx + ((size_t)((b << 10) + n)) * KK;
#pragma unroll
        for (int j = 0; j < 7; j++) o[j] = bi[j];
        o[7] = n;  // self loop appended last, like the reference
    }
}

// ---------------------------------------------------------------------------
// Register-blocked GEMM (exact R7 body), combined Wl/Wr via grid.y.
// ---------------------------------------------------------------------------
template<int FIN, int DOUT>
__global__ void __launch_bounds__(256) gemm2_kernel(
    const float* __restrict__ x,
    const float* __restrict__ Wa, const float* __restrict__ ba,
    const float* __restrict__ Wb, const float* __restrict__ bb,
    float* __restrict__ outa, float* __restrict__ outb)
{
    constexpr int CT  = DOUT / 16;
    constexpr int CU  = CT / 2;
    constexpr int CPT = (CT / 4 > 0) ? CT / 4 : 1;
    constexpr int RXf = 132;

    __shared__ float xs[FIN * RXf];
    __shared__ float ws[FIN * DOUT];
    __shared__ float sb[DOUT];

    const float* W    = blockIdx.y ? Wb   : Wa;
    const float* bias = blockIdx.y ? bb   : ba;
    float*       out  = blockIdx.y ? outb : outa;

    int tid  = threadIdx.x;
    int base = blockIdx.x * 128;

    for (int i = tid; i < FIN * DOUT; i += 256) {
        int k = i / DOUT, c = i - k * DOUT;
        int q = c >> 2;
        int phys = (q % CPT) * 16 + (q / CPT);
        ws[k * DOUT + phys * 4 + (c & 3)] = W[i];
    }
    if (tid < DOUT) sb[tid] = bias[tid];
    for (int i = tid; i < 128 * FIN; i += 256) {
        int r = i / FIN, k = i - r * FIN;
        xs[k * RXf + r] = x[(size_t)(base + r) * FIN + k];
    }
    __syncthreads();

    int tx = tid & 15, ty = tid >> 4;
    int r0 = ty * 8, c0 = tx * CT;

    ull acc[8][CU];
    {
        const ull* bp = (const ull*)(sb + c0);
#pragma unroll
        for (int r = 0; r < 8; r++)
#pragma unroll
            for (int c = 0; c < CU; c++) acc[r][c] = bp[c];
    }

#pragma unroll 4
    for (int k = 0; k < FIN; k++) {
        const float4* xp = (const float4*)(xs + k * RXf + r0);
        float4 xa = xp[0], xb = xp[1];
        ull xv[8];
        xv[0] = bcast2(xa.x); xv[1] = bcast2(xa.y);
        xv[2] = bcast2(xa.z); xv[3] = bcast2(xa.w);
        xv[4] = bcast2(xb.x); xv[5] = bcast2(xb.y);
        xv[6] = bcast2(xb.z); xv[7] = bcast2(xb.w);

        ull wv[CU];
#pragma unroll
        for (int j = 0; j < CPT; j++) {
            ulonglong2 t = *(const ulonglong2*)(ws + k * DOUT + (j * 16 + tx) * 4);
            wv[2 * j] = t.x; wv[2 * j + 1] = t.y;
        }
#pragma unroll
        for (int r = 0; r < 8; r++)
#pragma unroll
            for (int c = 0; c < CU; c++)
                acc[r][c] = fma2(xv[r], wv[c], acc[r][c]);
    }

#pragma unroll
    for (int r = 0; r < 8; r++) {
        ulonglong2* op = (ulonglong2*)(out + (size_t)(base + r0 + r) * DOUT + c0);
#pragma unroll
        for (int c = 0; c < CU / 2; c++)
            op[c] = make_ulonglong2(acc[r][2 * c], acc[r][2 * c + 1]);
    }
}

// Single-matrix variant with row base (layer-1; 3 launches keep knn at idx3).
template<int FIN, int DOUT>
__global__ void __launch_bounds__(256) gemm1_kernel(
    const float* __restrict__ x,
    const float* __restrict__ W, const float* __restrict__ bias,
    float* __restrict__ out, int rowbase)
{
    constexpr int CT  = DOUT / 16;
    constexpr int CU  = CT / 2;
    constexpr int CPT = (CT / 4 > 0) ? CT / 4 : 1;
    constexpr int RXf = 132;

    __shared__ float xs[FIN * RXf];
    __shared__ float ws[FIN * DOUT];
    __shared__ float sb[DOUT];

    int tid  = threadIdx.x;
    int base = rowbase + blockIdx.x * 128;

    for (int i = tid; i < FIN * DOUT; i += 256) {
        int k = i / DOUT, c = i - k * DOUT;
        int q = c >> 2;
        int phys = (q % CPT) * 16 + (q / CPT);
        ws[k * DOUT + phys * 4 + (c & 3)] = W[i];
    }
    if (tid < DOUT) sb[tid] = bias[tid];
    for (int i = tid; i < 128 * FIN; i += 256) {
        int r = i / FIN, k = i - r * FIN;
        xs[k * RXf + r] = x[(size_t)(base + r) * FIN + k];
    }
    __syncthreads();

    int tx = tid & 15, ty = tid >> 4;
    int r0 = ty * 8, c0 = tx * CT;

    ull acc[8][CU];
    {
        const ull* bp = (const ull*)(sb + c0);
#pragma unroll
        for (int r = 0; r < 8; r++)
#pragma unroll
            for (int c = 0; c < CU; c++) acc[r][c] = bp[c];
    }

#pragma unroll 4
    for (int k = 0; k < FIN; k++) {
        const float4* xp = (const float4*)(xs + k * RXf + r0);
        float4 xa = xp[0], xb = xp[1];
        ull xv[8];
        xv[0] = bcast2(xa.x); xv[1] = bcast2(xa.y);
        xv[2] = bcast2(xa.z); xv[3] = bcast2(xa.w);
        xv[4] = bcast2(xb.x); xv[5] = bcast2(xb.y);
        xv[6] = bcast2(xb.z); xv[7] = bcast2(xb.w);

        ull wv[CU];
#pragma unroll
        for (int j = 0; j < CPT; j++) {
            ulonglong2 t = *(const ulonglong2*)(ws + k * DOUT + (j * 16 + tx) * 4);
            wv[2 * j] = t.x; wv[2 * j + 1] = t.y;
        }
#pragma unroll
        for (int r = 0; r < 8; r++)
#pragma unroll
            for (int c = 0; c < CU; c++)
                acc[r][c] = fma2(xv[r], wv[c], acc[r][c]);
    }

#pragma unroll
    for (int r = 0; r < 8; r++) {
        ulonglong2* op = (ulonglong2*)(out + (size_t)(base + r0 + r) * DOUT + c0);
#pragma unroll
        for (int c = 0; c < CU / 2; c++)
            op[c] = make_ulonglong2(acc[r][2 * c], acc[r][2 * c + 1]);
    }
}

// ---------------------------------------------------------------------------
// GATv2 attention + aggregation for layer 1, one warp per node.
// ---------------------------------------------------------------------------
__global__ void attn1_kernel(const float* __restrict__ xl, const float* __restrict__ xr,
                             const float* __restrict__ att, const float* __restrict__ bias,
                             float* __restrict__ out)
{
    constexpr int DOUT = D1, V = 2;
    int node = (blockIdx.x * blockDim.x + threadIdx.x) >> 5;
    int lane = threadIdx.x & 31;
    int b = node >> 10;
    const int* nidx = g_idx + (size_t)node * KK;
    int4 i0 = *(const int4*)nidx;
    int4 i1 = *(const int4*)(nidx + 4);
    int srcs[KK] = {i0.x, i0.y, i0.z, i0.w, i1.x, i1.y, i1.z, i1.w};

    int c0 = lane * V;

    float2 tr = *(const float2*)(xr + (size_t)node * DOUT + c0);
    float xrv[V] = {tr.x, tr.y};
    float2 ta = *(const float2*)(att + c0);
    float attv[V] = {ta.x, ta.y};

    float xnb[KK][V];
    float lg[KK];
#pragma unroll
    for (int k = 0; k < KK; k++) {
        int src = (b << 10) + srcs[k];
        float2 t = *(const float2*)(xl + (size_t)src * DOUT + c0);
        xnb[k][0] = t.x; xnb[k][1] = t.y;
        float s = 0.f;
#pragma unroll
        for (int v = 0; v < V; v++) {
            float e = xnb[k][v] + xrv[v];
            e = e > 0.f ? e : 0.2f * e;       // leaky_relu(0.2)
            s = fmaf(e, attv[v], s);
        }
        s += __shfl_xor_sync(0xffffffffu, s, 1);
        s += __shfl_xor_sync(0xffffffffu, s, 2);
        s += __shfl_xor_sync(0xffffffffu, s, 4);
        lg[k] = s;
    }

    float mx = lg[0];
#pragma unroll
    for (int k = 1; k < KK; k++) mx = fmaxf(mx, lg[k]);
    float ssum = 0.f;
#pragma unroll
    for (int k = 0; k < KK; k++) { lg[k] = __expf(lg[k] - mx); ssum += lg[k]; }
    float inv = 1.f / ssum;

    float o[V] = {0.f, 0.f};
#pragma unroll
    for (int k = 0; k < KK; k++) {
        float a = lg[k] * inv;
#pragma unroll
        for (int v = 0; v < V; v++) o[v] = fmaf(a, xnb[k][v], o[v]);
    }

    float2 bv = *(const float2*)(bias + c0);
    float2 r;
    r.x = fmaxf(o[0] + bv.x, 0.f);
    r.y = fmaxf(o[1] + bv.y, 0.f);
    *(float2*)(out + (size_t)node * DOUT + c0) = r;
}

// ---------------------------------------------------------------------------
// Layer-2 attention FUSED with partial mean-pool. 8 warps = 8 nodes/block;
// block partial (128 floats) to g_part.
// ---------------------------------------------------------------------------
__global__ void __launch_bounds__(256) attn2_pool_kernel(
    const float* __restrict__ xl, const float* __restrict__ xr,
    const float* __restrict__ att, const float* __restrict__ bias,
    float* __restrict__ part)
{
    constexpr int DOUT = D2, V = 4;
    __shared__ float sacc[8 * D2];

    int warp = threadIdx.x >> 5;
    int lane = threadIdx.x & 31;
    int node = blockIdx.x * 8 + warp;
    int b = node >> 10;
    const int* nidx = g_idx + (size_t)node * KK;
    int4 i0 = *(const int4*)nidx;
    int4 i1 = *(const int4*)(nidx + 4);
    int srcs[KK] = {i0.x, i0.y, i0.z, i0.w, i1.x, i1.y, i1.z, i1.w};

    int c0 = lane * V;

    float4 tr = *(const float4*)(xr + (size_t)node * DOUT + c0);
    float xrv[V] = {tr.x, tr.y, tr.z, tr.w};
    float4 ta = *(const float4*)(att + c0);
    float attv[V] = {ta.x, ta.y, ta.z, ta.w};

    float xnb[KK][V];
    float lg[KK];
#pragma unroll
    for (int k = 0; k < KK; k++) {
        int src = (b << 10) + srcs[k];
        float4 t = *(const float4*)(xl + (size_t)src * DOUT + c0);
        xnb[k][0] = t.x; xnb[k][1] = t.y; xnb[k][2] = t.z; xnb[k][3] = t.w;
        float s = 0.f;
#pragma unroll
        for (int v = 0; v < V; v++) {
            float e = xnb[k][v] + xrv[v];
            e = e > 0.f ? e : 0.2f * e;       // leaky_relu(0.2)
            s = fmaf(e, attv[v], s);
        }
        s += __shfl_xor_sync(0xffffffffu, s, 1);
        s += __shfl_xor_sync(0xffffffffu, s, 2);
        s += __shfl_xor_sync(0xffffffffu, s, 4);
        lg[k] = s;
    }

    float mx = lg[0];
#pragma unroll
    for (int k = 1; k < KK; k++) mx = fmaxf(mx, lg[k]);
    float ssum = 0.f;
#pragma unroll
    for (int k = 0; k < KK; k++) { lg[k] = __expf(lg[k] - mx); ssum += lg[k]; }
    float inv = 1.f / ssum;

    float o[V] = {0.f, 0.f, 0.f, 0.f};
#pragma unroll
    for (int k = 0; k < KK; k++) {
        float a = lg[k] * inv;
#pragma unroll
        for (int v = 0; v < V; v++) o[v] = fmaf(a, xnb[k][v], o[v]);
    }

    float4 bv = *(const float4*)(bias + c0);
    float4 r;
    r.x = fmaxf(o[0] + bv.x, 0.f);
    r.y = fmaxf(o[1] + bv.y, 0.f);
    r.z = fmaxf(o[2] + bv.z, 0.f);
    r.w = fmaxf(o[3] + bv.w, 0.f);
    *(float4*)(sacc + warp * D2 + c0) = r;
    __syncthreads();

    int t = threadIdx.x;
    if (t < D2) {
        float s = 0.f;
#pragma unroll
        for (int w = 0; w < 8; w++) s += sacc[w * D2 + t];
        part[(size_t)blockIdx.x * D2 + t] = s;
    }
}

// ---------------------------------------------------------------------------
// Final pool reduce: out[b][c] = (1/N) * sum over 128 block-partials.
// ---------------------------------------------------------------------------
__global__ void pool_reduce_kernel(const float* __restrict__ part,
                                   float* __restrict__ out)
{
    int b = blockIdx.x, t = threadIdx.x;  // 128 threads
    const float* p = part + (size_t)b * (NN / 8) * D2 + t;
    float s = 0.f;
#pragma unroll 8
    for (int j = 0; j < NN / 8; j++) s += p[(size_t)j * D2];
    out[b * D2 + t] = s * (1.f / (float)NN);
}

// ---------------------------------------------------------------------------
extern "C" void kernel_launch(void* const* d_in, const int* in_sizes, int n_in,
                              void* d_out, int out_size)
{
    const float* x     = (const float*)d_in[0];
    const float* pos   = (const float*)d_in[1];
    const float* Wl1   = (const float*)d_in[2];
    const float* bl1   = (const float*)d_in[3];
    const float* Wr1   = (const float*)d_in[4];
    const float* br1   = (const float*)d_in[5];
    const float* att1  = (const float*)d_in[6];
    const float* bias1 = (const float*)d_in[7];
    const float* Wl2   = (const float*)d_in[8];
    const float* bl2   = (const float*)d_in[9];
    const float* Wr2   = (const float*)d_in[10];
    const float* br2   = (const float*)d_in[11];
    const float* att2  = (const float*)d_in[12];
    const float* bias2 = (const float*)d_in[13];
    float* out = (float*)d_out;

    float *xl1, *xr1, *h1, *xl2, *xr2, *part;
    cudaGetSymbolAddress((void**)&xl1,  g_xl1);
    cudaGetSymbolAddress((void**)&xr1,  g_xr1);
    cudaGetSymbolAddress((void**)&h1,   g_h1);
    cudaGetSymbolAddress((void**)&xl2,  g_xl2);
    cudaGetSymbolAddress((void**)&xr2,  g_xr2);
    cudaGetSymbolAddress((void**)&part, g_part);

    // idx0-2: layer-1 transforms (Wl split in two so knn lands at idx3)
    gemm1_kernel<F1, D1><<<256, 256>>>(x, Wl1, bl1, xl1, 0);
    gemm1_kernel<F1, D1><<<256, 256>>>(x, Wl1, bl1, xl1, 32768);
    gemm1_kernel<F1, D1><<<512, 256>>>(x, Wr1, br1, xr1, 0);
    // idx3: KNN graph (PROFILED) — 4 threads/node, bank-skewed quarters
    knn_kernel<<<dim3(16, BB), 256>>>(pos);
    // idx4: layer-1 attention + ReLU
    attn1_kernel<<<(BB * NN * 32) / 256, 256>>>(xl1, xr1, att1, bias1, h1);
    // idx5: layer-2 transforms (combined grid.y picks Wl/Wr — R7 config)
    gemm2_kernel<D1, D2><<<dim3(BB * NN / 128, 2), 256>>>(
        h1, Wl2, bl2, Wr2, br2, xl2, xr2);
    // idx6: layer-2 attention + ReLU fused with partial mean pool
    attn2_pool_kernel<<<BB * NN / 8, 256>>>(xl2, xr2, att2, bias2, part);
    // idx7: final pool reduction
    pool_reduce_kernel<<<BB, 128>>>(part, out);
}

// round 14
// speedup vs baseline: 1.1842x; 1.1842x over previous
#include <cuda_runtime.h>
#include <cfloat>

#define BB 64
#define NN 1024
#define KK 8     // 7 knn + self
#define F1 16
#define D1 64    // H1*C1 = 4*16
#define D2 128   // H2*C2 = 4*32

typedef unsigned long long ull;
typedef unsigned int u32;

// Scratch (allocation-free rule: __device__ globals)
__device__ float g_xl1[BB * NN * D1];
__device__ float g_xr1[BB * NN * D1];
__device__ float g_h1 [BB * NN * D1];
__device__ float g_xl2[BB * NN * D2];
__device__ float g_xr2[BB * NN * D2];
__device__ float g_part[BB * (NN / 8) * D2];   // attn2+pool partials (4MB)
__device__ int   g_idx[BB * NN * KK];

// Packed dual-fp32 ops (sm_103a f32x2 pipe — ptxas never emits from C++)
__device__ __forceinline__ ull fma2(ull a, ull b, ull c) {
    ull d;
    asm("fma.rn.f32x2 %0, %1, %2, %3;" : "=l"(d) : "l"(a), "l"(b), "l"(c));
    return d;
}
__device__ __forceinline__ ull add2(ull a, ull b) {
    ull d;
    asm("add.rn.f32x2 %0, %1, %2;" : "=l"(d) : "l"(a), "l"(b));
    return d;
}
__device__ __forceinline__ ull bcast2(float v) {
    ull d;
    asm("mov.b64 %0, {%1, %1};" : "=l"(d) : "r"(__float_as_uint(v)));
    return d;
}
__device__ __forceinline__ float lo32(ull v) { return __uint_as_float((u32)v); }
__device__ __forceinline__ float hi32(ull v) { return __uint_as_float((u32)(v >> 32)); }

// ---------------------------------------------------------------------------
// KNN, branchless two-phase. One thread per node (R11 grid: 4 x 64 blocks).
// Phase 1: exact 7th-smallest distance via UNCONDITIONAL sorted-bubble
//   (min/max chains, no branches, no divergence). Even/odd candidate streams
//   keep two independent 7-lists (halves the dependency depth), merged once.
// Phase 2: rescan, collect indices with d <= d7 in index order (bit-identical
//   recompute) into per-thread smem slots -> exact stable top-7 incl. ties.
// ---------------------------------------------------------------------------
__global__ void knn_kernel(const float* __restrict__ pos)
{
    __shared__ float spp[NN * 4];       // pair-interleaved SoA: 16KB
    __shared__ int   sidx[8 * 256];     // phase-2 collection: 8KB

    int b = blockIdx.y;
    const float* p = pos + (size_t)b * NN * 3;
    for (int i = threadIdx.x; i < NN; i += blockDim.x) {
        float x = p[i * 3 + 0], y = p[i * 3 + 1], z = p[i * 3 + 2];
        float w = x * x + y * y + z * z;
        float* q = spp + (i >> 1) * 8 + (i & 1);
        q[0] = x; q[2] = y; q[4] = z; q[6] = w;
    }
    __syncthreads();

    int tid = threadIdx.x;
    int n = blockIdx.x * 256 + tid;     // node 0..1023
    const float* meq = spp + (n >> 1) * 8 + (n & 1);
    float mex = meq[0], mey = meq[2], mez = meq[4], mew = meq[6];
    ull cx = bcast2(-2.f * mex), cy = bcast2(-2.f * mey),
        cz = bcast2(-2.f * mez), cw = bcast2(mew);

    int  pn    = n >> 1;
    bool nEven = (n & 1) == 0;

    float ev[7], od[7];
#pragma unroll
    for (int j = 0; j < 7; j++) { ev[j] = FLT_MAX; od[j] = FLT_MAX; }

    const ulonglong2* pp = (const ulonglong2*)spp;

    // ---- Phase 1: branchless distance-only top-7 (two streams) ----
#pragma unroll 2
    for (int i = 0; i < NN / 2; i++) {
        ulonglong2 a  = pp[2 * i];      // {x0x1, y0y1}
        ulonglong2 c2 = pp[2 * i + 1];  // {z0z1, w0w1}
        ull d2 = add2(c2.y, cw);
        d2 = fma2(cx, a.x, d2);
        d2 = fma2(cy, a.y, d2);
        d2 = fma2(cz, c2.x, d2);
        float d0 = lo32(d2), d1 = hi32(d2);
        if (i == pn) { if (nEven) d0 = FLT_MAX; else d1 = FLT_MAX; }  // self
#pragma unroll
        for (int j = 0; j < 7; j++) {   // two independent min/max chains
            float l0 = fminf(ev[j], d0); d0 = fmaxf(ev[j], d0); ev[j] = l0;
            float l1 = fminf(od[j], d1); d1 = fmaxf(od[j], d1); od[j] = l1;
        }
    }
    // merge odd-stream list into even-stream list -> global 7 smallest
#pragma unroll
    for (int k = 0; k < 7; k++) {
        float x = od[k];
#pragma unroll
        for (int j = 0; j < 7; j++) {
            float lo = fminf(ev[j], x); x = fmaxf(ev[j], x); ev[j] = lo;
        }
    }
    float d7 = ev[6];   // exact 7th-smallest (ties included via <= below)

    // ---- Phase 2: index recovery, stable order ----
    int cnt = 0;
#pragma unroll 2
    for (int i = 0; i < NN / 2; i++) {
        ulonglong2 a  = pp[2 * i];
        ulonglong2 c2 = pp[2 * i + 1];
        ull d2 = add2(c2.y, cw);
        d2 = fma2(cx, a.x, d2);
        d2 = fma2(cy, a.y, d2);
        d2 = fma2(cz, c2.x, d2);
        float d0 = lo32(d2), d1 = hi32(d2);
        if (i == pn) { if (nEven) d0 = FLT_MAX; else d1 = FLT_MAX; }
        if (d0 <= d7 && cnt < 8) { sidx[cnt * 256 + tid] = 2 * i;     cnt++; }
        if (d1 <= d7 && cnt < 8) { sidx[cnt * 256 + tid] = 2 * i + 1; cnt++; }
    }

    int* o = g_idx + ((size_t)((b << 10) + n)) * KK;
#pragma unroll
    for (int j = 0; j < 7; j++) o[j] = sidx[j * 256 + tid];
    o[7] = n;  // self loop appended last, like the reference
}

// ---------------------------------------------------------------------------
// Register-blocked GEMM (exact R7 body), combined Wl/Wr via grid.y.
// ---------------------------------------------------------------------------
template<int FIN, int DOUT>
__global__ void __launch_bounds__(256) gemm2_kernel(
    const float* __restrict__ x,
    const float* __restrict__ Wa, const float* __restrict__ ba,
    const float* __restrict__ Wb, const float* __restrict__ bb,
    float* __restrict__ outa, float* __restrict__ outb)
{
    constexpr int CT  = DOUT / 16;
    constexpr int CU  = CT / 2;
    constexpr int CPT = (CT / 4 > 0) ? CT / 4 : 1;
    constexpr int RXf = 132;

    __shared__ float xs[FIN * RXf];
    __shared__ float ws[FIN * DOUT];
    __shared__ float sb[DOUT];

    const float* W    = blockIdx.y ? Wb   : Wa;
    const float* bias = blockIdx.y ? bb   : ba;
    float*       out  = blockIdx.y ? outb : outa;

    int tid  = threadIdx.x;
    int base = blockIdx.x * 128;

    for (int i = tid; i < FIN * DOUT; i += 256) {
        int k = i / DOUT, c = i - k * DOUT;
        int q = c >> 2;
        int phys = (q % CPT) * 16 + (q / CPT);
        ws[k * DOUT + phys * 4 + (c & 3)] = W[i];
    }
    if (tid < DOUT) sb[tid] = bias[tid];
    for (int i = tid; i < 128 * FIN; i += 256) {
        int r = i / FIN, k = i - r * FIN;
        xs[k * RXf + r] = x[(size_t)(base + r) * FIN + k];
    }
    __syncthreads();

    int tx = tid & 15, ty = tid >> 4;
    int r0 = ty * 8, c0 = tx * CT;

    ull acc[8][CU];
    {
        const ull* bp = (const ull*)(sb + c0);
#pragma unroll
        for (int r = 0; r < 8; r++)
#pragma unroll
            for (int c = 0; c < CU; c++) acc[r][c] = bp[c];
    }

#pragma unroll 4
    for (int k = 0; k < FIN; k++) {
        const float4* xp = (const float4*)(xs + k * RXf + r0);
        float4 xa = xp[0], xb = xp[1];
        ull xv[8];
        xv[0] = bcast2(xa.x); xv[1] = bcast2(xa.y);
        xv[2] = bcast2(xa.z); xv[3] = bcast2(xa.w);
        xv[4] = bcast2(xb.x); xv[5] = bcast2(xb.y);
        xv[6] = bcast2(xb.z); xv[7] = bcast2(xb.w);

        ull wv[CU];
#pragma unroll
        for (int j = 0; j < CPT; j++) {
            ulonglong2 t = *(const ulonglong2*)(ws + k * DOUT + (j * 16 + tx) * 4);
            wv[2 * j] = t.x; wv[2 * j + 1] = t.y;
        }
#pragma unroll
        for (int r = 0; r < 8; r++)
#pragma unroll
            for (int c = 0; c < CU; c++)
                acc[r][c] = fma2(xv[r], wv[c], acc[r][c]);
    }

#pragma unroll
    for (int r = 0; r < 8; r++) {
        ulonglong2* op = (ulonglong2*)(out + (size_t)(base + r0 + r) * DOUT + c0);
#pragma unroll
        for (int c = 0; c < CU / 2; c++)
            op[c] = make_ulonglong2(acc[r][2 * c], acc[r][2 * c + 1]);
    }
}

// Single-matrix variant with row base (layer-1; 3 launches keep knn at idx3).
template<int FIN, int DOUT>
__global__ void __launch_bounds__(256) gemm1_kernel(
    const float* __restrict__ x,
    const float* __restrict__ W, const float* __restrict__ bias,
    float* __restrict__ out, int rowbase)
{
    constexpr int CT  = DOUT / 16;
    constexpr int CU  = CT / 2;
    constexpr int CPT = (CT / 4 > 0) ? CT / 4 : 1;
    constexpr int RXf = 132;

    __shared__ float xs[FIN * RXf];
    __shared__ float ws[FIN * DOUT];
    __shared__ float sb[DOUT];

    int tid  = threadIdx.x;
    int base = rowbase + blockIdx.x * 128;

    for (int i = tid; i < FIN * DOUT; i += 256) {
        int k = i / DOUT, c = i - k * DOUT;
        int q = c >> 2;
        int phys = (q % CPT) * 16 + (q / CPT);
        ws[k * DOUT + phys * 4 + (c & 3)] = W[i];
    }
    if (tid < DOUT) sb[tid] = bias[tid];
    for (int i = tid; i < 128 * FIN; i += 256) {
        int r = i / FIN, k = i - r * FIN;
        xs[k * RXf + r] = x[(size_t)(base + r) * FIN + k];
    }
    __syncthreads();

    int tx = tid & 15, ty = tid >> 4;
    int r0 = ty * 8, c0 = tx * CT;

    ull acc[8][CU];
    {
        const ull* bp = (const ull*)(sb + c0);
#pragma unroll
        for (int r = 0; r < 8; r++)
#pragma unroll
            for (int c = 0; c < CU; c++) acc[r][c] = bp[c];
    }

#pragma unroll 4
    for (int k = 0; k < FIN; k++) {
        const float4* xp = (const float4*)(xs + k * RXf + r0);
        float4 xa = xp[0], xb = xp[1];
        ull xv[8];
        xv[0] = bcast2(xa.x); xv[1] = bcast2(xa.y);
        xv[2] = bcast2(xa.z); xv[3] = bcast2(xa.w);
        xv[4] = bcast2(xb.x); xv[5] = bcast2(xb.y);
        xv[6] = bcast2(xb.z); xv[7] = bcast2(xb.w);

        ull wv[CU];
#pragma unroll
        for (int j = 0; j < CPT; j++) {
            ulonglong2 t = *(const ulonglong2*)(ws + k * DOUT + (j * 16 + tx) * 4);
            wv[2 * j] = t.x; wv[2 * j + 1] = t.y;
        }
#pragma unroll
        for (int r = 0; r < 8; r++)
#pragma unroll
            for (int c = 0; c < CU; c++)
                acc[r][c] = fma2(xv[r], wv[c], acc[r][c]);
    }

#pragma unroll
    for (int r = 0; r < 8; r++) {
        ulonglong2* op = (ulonglong2*)(out + (size_t)(base + r0 + r) * DOUT + c0);
#pragma unroll
        for (int c = 0; c < CU / 2; c++)
            op[c] = make_ulonglong2(acc[r][2 * c], acc[r][2 * c + 1]);
    }
}

// ---------------------------------------------------------------------------
// GATv2 attention + aggregation for layer 1, one warp per node.
// ---------------------------------------------------------------------------
__global__ void attn1_kernel(const float* __restrict__ xl, const float* __restrict__ xr,
                             const float* __restrict__ att, const float* __restrict__ bias,
                             float* __restrict__ out)
{
    constexpr int DOUT = D1, V = 2;
    int node = (blockIdx.x * blockDim.x + threadIdx.x) >> 5;
    int lane = threadIdx.x & 31;
    int b = node >> 10;
    const int* nidx = g_idx + (size_t)node * KK;
    int4 i0 = *(const int4*)nidx;
    int4 i1 = *(const int4*)(nidx + 4);
    int srcs[KK] = {i0.x, i0.y, i0.z, i0.w, i1.x, i1.y, i1.z, i1.w};

    int c0 = lane * V;

    float2 tr = *(const float2*)(xr + (size_t)node * DOUT + c0);
    float xrv[V] = {tr.x, tr.y};
    float2 ta = *(const float2*)(att + c0);
    float attv[V] = {ta.x, ta.y};

    float xnb[KK][V];
    float lg[KK];
#pragma unroll
    for (int k = 0; k < KK; k++) {
        int src = (b << 10) + srcs[k];
        float2 t = *(const float2*)(xl + (size_t)src * DOUT + c0);
        xnb[k][0] = t.x; xnb[k][1] = t.y;
        float s = 0.f;
#pragma unroll
        for (int v = 0; v < V; v++) {
            float e = xnb[k][v] + xrv[v];
            e = e > 0.f ? e : 0.2f * e;       // leaky_relu(0.2)
            s = fmaf(e, attv[v], s);
        }
        s += __shfl_xor_sync(0xffffffffu, s, 1);
        s += __shfl_xor_sync(0xffffffffu, s, 2);
        s += __shfl_xor_sync(0xffffffffu, s, 4);
        lg[k] = s;
    }

    float mx = lg[0];
#pragma unroll
    for (int k = 1; k < KK; k++) mx = fmaxf(mx, lg[k]);
    float ssum = 0.f;
#pragma unroll
    for (int k = 0; k < KK; k++) { lg[k] = __expf(lg[k] - mx); ssum += lg[k]; }
    float inv = 1.f / ssum;

    float o[V] = {0.f, 0.f};
#pragma unroll
    for (int k = 0; k < KK; k++) {
        float a = lg[k] * inv;
#pragma unroll
        for (int v = 0; v < V; v++) o[v] = fmaf(a, xnb[k][v], o[v]);
    }

    float2 bv = *(const float2*)(bias + c0);
    float2 r;
    r.x = fmaxf(o[0] + bv.x, 0.f);
    r.y = fmaxf(o[1] + bv.y, 0.f);
    *(float2*)(out + (size_t)node * DOUT + c0) = r;
}

// ---------------------------------------------------------------------------
// Layer-2 attention FUSED with partial mean-pool. 8 warps = 8 nodes/block;
// block partial (128 floats) to g_part.
// ---------------------------------------------------------------------------
__global__ void __launch_bounds__(256) attn2_pool_kernel(
    const float* __restrict__ xl, const float* __restrict__ xr,
    const float* __restrict__ att, const float* __restrict__ bias,
    float* __restrict__ part)
{
    constexpr int DOUT = D2, V = 4;
    __shared__ float sacc[8 * D2];

    int warp = threadIdx.x >> 5;
    int lane = threadIdx.x & 31;
    int node = blockIdx.x * 8 + warp;
    int b = node >> 10;
    const int* nidx = g_idx + (size_t)node * KK;
    int4 i0 = *(const int4*)nidx;
    int4 i1 = *(const int4*)(nidx + 4);
    int srcs[KK] = {i0.x, i0.y, i0.z, i0.w, i1.x, i1.y, i1.z, i1.w};

    int c0 = lane * V;

    float4 tr = *(const float4*)(xr + (size_t)node * DOUT + c0);
    float xrv[V] = {tr.x, tr.y, tr.z, tr.w};
    float4 ta = *(const float4*)(att + c0);
    float attv[V] = {ta.x, ta.y, ta.z, ta.w};

    float xnb[KK][V];
    float lg[KK];
#pragma unroll
    for (int k = 0; k < KK; k++) {
        int src = (b << 10) + srcs[k];
        float4 t = *(const float4*)(xl + (size_t)src * DOUT + c0);
        xnb[k][0] = t.x; xnb[k][1] = t.y; xnb[k][2] = t.z; xnb[k][3] = t.w;
        float s = 0.f;
#pragma unroll
        for (int v = 0; v < V; v++) {
            float e = xnb[k][v] + xrv[v];
            e = e > 0.f ? e : 0.2f * e;       // leaky_relu(0.2)
            s = fmaf(e, attv[v], s);
        }
        s += __shfl_xor_sync(0xffffffffu, s, 1);
        s += __shfl_xor_sync(0xffffffffu, s, 2);
        s += __shfl_xor_sync(0xffffffffu, s, 4);
        lg[k] = s;
    }

    float mx = lg[0];
#pragma unroll
    for (int k = 1; k < KK; k++) mx = fmaxf(mx, lg[k]);
    float ssum = 0.f;
#pragma unroll
    for (int k = 0; k < KK; k++) { lg[k] = __expf(lg[k] - mx); ssum += lg[k]; }
    float inv = 1.f / ssum;

    float o[V] = {0.f, 0.f, 0.f, 0.f};
#pragma unroll
    for (int k = 0; k < KK; k++) {
        float a = lg[k] * inv;
#pragma unroll
        for (int v = 0; v < V; v++) o[v] = fmaf(a, xnb[k][v], o[v]);
    }

    float4 bv = *(const float4*)(bias + c0);
    float4 r;
    r.x = fmaxf(o[0] + bv.x, 0.f);
    r.y = fmaxf(o[1] + bv.y, 0.f);
    r.z = fmaxf(o[2] + bv.z, 0.f);
    r.w = fmaxf(o[3] + bv.w, 0.f);
    *(float4*)(sacc + warp * D2 + c0) = r;
    __syncthreads();

    int t = threadIdx.x;
    if (t < D2) {
        float s = 0.f;
#pragma unroll
        for (int w = 0; w < 8; w++) s += sacc[w * D2 + t];
        part[(size_t)blockIdx.x * D2 + t] = s;
    }
}

// ---------------------------------------------------------------------------
// Final pool reduce: out[b][c] = (1/N) * sum over 128 block-partials.
// ---------------------------------------------------------------------------
__global__ void pool_reduce_kernel(const float* __restrict__ part,
                                   float* __restrict__ out)
{
    int b = blockIdx.x, t = threadIdx.x;  // 128 threads
    const float* p = part + (size_t)b * (NN / 8) * D2 + t;
    float s = 0.f;
#pragma unroll 8
    for (int j = 0; j < NN / 8; j++) s += p[(size_t)j * D2];
    out[b * D2 + t] = s * (1.f / (float)NN);
}

// ---------------------------------------------------------------------------
extern "C" void kernel_launch(void* const* d_in, const int* in_sizes, int n_in,
                              void* d_out, int out_size)
{
    const float* x     = (const float*)d_in[0];
    const float* pos   = (const float*)d_in[1];
    const float* Wl1   = (const float*)d_in[2];
    const float* bl1   = (const float*)d_in[3];
    const float* Wr1   = (const float*)d_in[4];
    const float* br1   = (const float*)d_in[5];
    const float* att1  = (const float*)d_in[6];
    const float* bias1 = (const float*)d_in[7];
    const float* Wl2   = (const float*)d_in[8];
    const float* bl2   = (const float*)d_in[9];
    const float* Wr2   = (const float*)d_in[10];
    const float* br2   = (const float*)d_in[11];
    const float* att2  = (const float*)d_in[12];
    const float* bias2 = (const float*)d_in[13];
    float* out = (float*)d_out;

    float *xl1, *xr1, *h1, *xl2, *xr2, *part;
    cudaGetSymbolAddress((void**)&xl1,  g_xl1);
    cudaGetSymbolAddress((void**)&xr1,  g_xr1);
    cudaGetSymbolAddress((void**)&h1,   g_h1);
    cudaGetSymbolAddress((void**)&xl2,  g_xl2);
    cudaGetSymbolAddress((void**)&xr2,  g_xr2);
    cudaGetSymbolAddress((void**)&part, g_part);

    // idx0-2: layer-1 transforms (Wl split in two so knn lands at idx3)
    gemm1_kernel<F1, D1><<<256, 256>>>(x, Wl1, bl1, xl1, 0);
    gemm1_kernel<F1, D1><<<256, 256>>>(x, Wl1, bl1, xl1, 32768);
    gemm1_kernel<F1, D1><<<512, 256>>>(x, Wr1, br1, xr1, 0);
    // idx3: KNN graph (PROFILED) — branchless two-phase, 1 thread/node
    knn_kernel<<<dim3(NN / 256, BB), 256>>>(pos);
    // idx4: layer-1 attention + ReLU
    attn1_kernel<<<(BB * NN * 32) / 256, 256>>>(xl1, xr1, att1, bias1, h1);
    // idx5: layer-2 transforms (combined grid.y picks Wl/Wr — R7 config)
    gemm2_kernel<D1, D2><<<dim3(BB * NN / 128, 2), 256>>>(
        h1, Wl2, bl2, Wr2, br2, xl2, xr2);
    // idx6: layer-2 attention + ReLU fused with partial mean pool
    attn2_pool_kernel<<<BB * NN / 8, 256>>>(xl2, xr2, att2, bias2, part);
    // idx7: final pool reduction
    pool_reduce_kernel<<<BB, 128>>>(part, out);
}

// round 15
// speedup vs baseline: 1.3822x; 1.1672x over previous
#include <cuda_runtime.h>
#include <cfloat>

#define BB 64
#define NN 1024
#define KK 8     // 7 knn + self
#define F1 16
#define D1 64    // H1*C1 = 4*16
#define D2 128   // H2*C2 = 4*32

typedef unsigned long long ull;
typedef unsigned int u32;

// Scratch (allocation-free rule: __device__ globals)
__device__ float g_xl1[BB * NN * D1];
__device__ float g_xr1[BB * NN * D1];
__device__ float g_h1 [BB * NN * D1];
__device__ float g_xl2[BB * NN * D2];
__device__ float g_xr2[BB * NN * D2];
__device__ float g_part[BB * (NN / 8) * D2];   // attn2+pool partials (4MB)
__device__ int   g_idx[BB * NN * KK];

// Packed dual-fp32 ops (sm_103a f32x2 pipe — ptxas never emits from C++)
__device__ __forceinline__ ull fma2(ull a, ull b, ull c) {
    ull d;
    asm("fma.rn.f32x2 %0, %1, %2, %3;" : "=l"(d) : "l"(a), "l"(b), "l"(c));
    return d;
}
__device__ __forceinline__ ull add2(ull a, ull b) {
    ull d;
    asm("add.rn.f32x2 %0, %1, %2;" : "=l"(d) : "l"(a), "l"(b));
    return d;
}
__device__ __forceinline__ ull bcast2(float v) {
    ull d;
    asm("mov.b64 %0, {%1, %1};" : "=l"(d) : "r"(__float_as_uint(v)));
    return d;
}
__device__ __forceinline__ float lo32(ull v) { return __uint_as_float((u32)v); }
__device__ __forceinline__ float hi32(ull v) { return __uint_as_float((u32)(v >> 32)); }

// Half-region stride in floats: 256 pairs * 8 + 8 pad -> byte delta 8224
// -> bank shift 8 between the two half-groups in a warp: conflict-free.
#define HSTRIDE 2056

// ---------------------------------------------------------------------------
// KNN, pair-min threshold + 2 threads/node. Thread (node, h) scans pair-half
// [h*256,(h+1)*256).
// Phase 1 (branchless): bubble pair-min through a sorted 7-list (15 FMNMX /
//   pair). Cross-half shfl merge -> t = 7th-smallest pair-min. EXACT bound:
//   at most 6 elements lie strictly below d7, so at most 6 pair-mins < d7
//   => t >= d7 => the d<=t filter catches every top-7 element.
// Phase 2: recompute (bit-identical), collect indices with d <= t (<=16/half)
//   in index order into smem slots.
// Final: half-0 thread runs exact stable top-7 (strict-< insert, index order)
//   over the <=~14 collected candidates. Ties at d7 resolved like lax.top_k.
// Block = 256 threads = 128 nodes; grid = (8, 64 batches) = 512 blocks.
// ---------------------------------------------------------------------------
__global__ void knn_kernel(const float* __restrict__ pos)
{
    __shared__ __align__(16) float spp[2 * HSTRIDE];   // ~16.4KB
    __shared__ int sidx[32 * 128];                     // 16KB (16 slots/half)

    int b = blockIdx.y;
    const float* p = pos + (size_t)b * NN * 3;
    for (int i = threadIdx.x; i < NN; i += 256) {
        float x = p[i * 3 + 0], y = p[i * 3 + 1], z = p[i * 3 + 2];
        float w = x * x + y * y + z * z;
        int pair = i >> 1;
        float* dst = spp + (pair >> 8) * HSTRIDE + (pair & 255) * 8 + (i & 1);
        dst[0] = x; dst[2] = y; dst[4] = z; dst[6] = w;
    }
    __syncthreads();

    int tid = threadIdx.x;
    int h   = tid & 1;                  // pair-half 0/1
    int nl  = tid >> 1;                 // node local 0..127
    int n   = blockIdx.x * 128 + nl;    // node 0..1023

    int pr0 = n >> 1;
    const float* meq = spp + (pr0 >> 8) * HSTRIDE + (pr0 & 255) * 8 + (n & 1);
    float mex = meq[0], mey = meq[2], mez = meq[4], mew = meq[6];
    float cxs = -2.f * mex, cys = -2.f * mey, czs = -2.f * mez;
    ull cx = bcast2(cxs), cy = bcast2(cys), cz = bcast2(czs), cw = bcast2(mew);

    int  pn    = n >> 1;
    bool nEven = (n & 1) == 0;

    float lst[7];
#pragma unroll
    for (int j = 0; j < 7; j++) lst[j] = FLT_MAX;

    const ulonglong2* pp = (const ulonglong2*)(spp + h * HSTRIDE);
    int pbase = h * 256;

    // ---- Phase 1: branchless pair-min top-7 ----
#pragma unroll 2
    for (int i = 0; i < 256; i++) {
        ulonglong2 a  = pp[2 * i];      // {x0x1, y0y1}
        ulonglong2 c2 = pp[2 * i + 1];  // {z0z1, w0w1}
        ull d2 = add2(c2.y, cw);
        d2 = fma2(cx, a.x, d2);
        d2 = fma2(cy, a.y, d2);
        d2 = fma2(cz, c2.x, d2);
        float d0 = lo32(d2), d1 = hi32(d2);
        float pm = fminf(d0, d1);
        if (pbase + i == pn) pm = nEven ? d1 : d0;   // exclude self from min
#pragma unroll
        for (int j = 0; j < 7; j++) {
            float l = fminf(lst[j], pm); pm = fmaxf(lst[j], pm); lst[j] = l;
        }
    }
    // Merge partner half's sorted 7-list (both lanes get identical result)
    {
        float ol[7];
#pragma unroll
        for (int j = 0; j < 7; j++) ol[j] = __shfl_xor_sync(0xffffffffu, lst[j], 1);
#pragma unroll
        for (int k = 0; k < 7; k++) {
            float x = ol[k];
#pragma unroll
            for (int j = 0; j < 7; j++) {
                float l = fminf(lst[j], x); x = fmaxf(lst[j], x); lst[j] = l;
            }
        }
    }
    float t = lst[6];   // 7th-smallest pair-min >= d7 (exact bound)

    // ---- Phase 2: collect indices with d <= t (index order, per half) ----
    int cnt = 0;
    int sbase = h * 16;
#pragma unroll 2
    for (int i = 0; i < 256; i++) {
        ulonglong2 a  = pp[2 * i];
        ulonglong2 c2 = pp[2 * i + 1];
        ull d2 = add2(c2.y, cw);
        d2 = fma2(cx, a.x, d2);
        d2 = fma2(cy, a.y, d2);
        d2 = fma2(cz, c2.x, d2);
        float d0 = lo32(d2), d1 = hi32(d2);
        if (pbase + i == pn) { if (nEven) d0 = FLT_MAX; else d1 = FLT_MAX; }
        if (d0 <= t && cnt < 16) { sidx[(sbase + cnt) * 128 + nl] = (pbase + i) * 2;     cnt++; }
        if (d1 <= t && cnt < 16) { sidx[(sbase + cnt) * 128 + nl] = (pbase + i) * 2 + 1; cnt++; }
    }

    int lane  = tid & 31;
    int cntA = __shfl_sync(0xffffffffu, cnt, lane & ~1);        // half-0 count
    int cntB = __shfl_sync(0xffffffffu, cnt, (lane & ~1) | 1);  // half-1 count
    __syncwarp();

    // ---- Final: exact stable top-7 over collected candidates (half 0) ----
    if (h == 0) {
        float bd[7]; int bi[7];
#pragma unroll
        for (int j = 0; j < 7; j++) { bd[j] = FLT_MAX; bi[j] = 0; }
#pragma unroll 1
        for (int jj = 0; jj < cntA + cntB; jj++) {
            int slot = (jj < cntA) ? jj : (16 + jj - cntA);
            int idx  = sidx[slot * 128 + nl];
            int prr  = idx >> 1;
            const float* q = spp + (prr >> 8) * HSTRIDE + (prr & 255) * 8 + (idx & 1);
            float d = q[6] + mew;          // bit-identical recompute
            d = fmaf(cxs, q[0], d);
            d = fmaf(cys, q[2], d);
            d = fmaf(czs, q[4], d);
            if (d < bd[6]) {
                bd[6] = d; bi[6] = idx;
#pragma unroll
                for (int j = 6; j > 0; j--) {
                    if (bd[j] < bd[j - 1]) {   // strict: ties keep earlier index
                        float td = bd[j]; bd[j] = bd[j - 1]; bd[j - 1] = td;
                        int   ti = bi[j]; bi[j] = bi[j - 1]; bi[j - 1] = ti;
                    }
                }
            }
        }
        int* o = g_idx + ((size_t)((b << 10) + n)) * KK;
#pragma unroll
        for (int j = 0; j < 7; j++) o[j] = bi[j];
        o[7] = n;  // self loop appended last, like the reference
    }
}

// ---------------------------------------------------------------------------
// Register-blocked GEMM (exact R7 body), combined Wl/Wr via grid.y.
// ---------------------------------------------------------------------------
template<int FIN, int DOUT>
__global__ void __launch_bounds__(256) gemm2_kernel(
    const float* __restrict__ x,
    const float* __restrict__ Wa, const float* __restrict__ ba,
    const float* __restrict__ Wb, const float* __restrict__ bb,
    float* __restrict__ outa, float* __restrict__ outb)
{
    constexpr int CT  = DOUT / 16;
    constexpr int CU  = CT / 2;
    constexpr int CPT = (CT / 4 > 0) ? CT / 4 : 1;
    constexpr int RXf = 132;

    __shared__ float xs[FIN * RXf];
    __shared__ float ws[FIN * DOUT];
    __shared__ float sb[DOUT];

    const float* W    = blockIdx.y ? Wb   : Wa;
    const float* bias = blockIdx.y ? bb   : ba;
    float*       out  = blockIdx.y ? outb : outa;

    int tid  = threadIdx.x;
    int base = blockIdx.x * 128;

    for (int i = tid; i < FIN * DOUT; i += 256) {
        int k = i / DOUT, c = i - k * DOUT;
        int q = c >> 2;
        int phys = (q % CPT) * 16 + (q / CPT);
        ws[k * DOUT + phys * 4 + (c & 3)] = W[i];
    }
    if (tid < DOUT) sb[tid] = bias[tid];
    for (int i = tid; i < 128 * FIN; i += 256) {
        int r = i / FIN, k = i - r * FIN;
        xs[k * RXf + r] = x[(size_t)(base + r) * FIN + k];
    }
    __syncthreads();

    int tx = tid & 15, ty = tid >> 4;
    int r0 = ty * 8, c0 = tx * CT;

    ull acc[8][CU];
    {
        const ull* bp = (const ull*)(sb + c0);
#pragma unroll
        for (int r = 0; r < 8; r++)
#pragma unroll
            for (int c = 0; c < CU; c++) acc[r][c] = bp[c];
    }

#pragma unroll 4
    for (int k = 0; k < FIN; k++) {
        const float4* xp = (const float4*)(xs + k * RXf + r0);
        float4 xa = xp[0], xb = xp[1];
        ull xv[8];
        xv[0] = bcast2(xa.x); xv[1] = bcast2(xa.y);
        xv[2] = bcast2(xa.z); xv[3] = bcast2(xa.w);
        xv[4] = bcast2(xb.x); xv[5] = bcast2(xb.y);
        xv[6] = bcast2(xb.z); xv[7] = bcast2(xb.w);

        ull wv[CU];
#pragma unroll
        for (int j = 0; j < CPT; j++) {
            ulonglong2 t = *(const ulonglong2*)(ws + k * DOUT + (j * 16 + tx) * 4);
            wv[2 * j] = t.x; wv[2 * j + 1] = t.y;
        }
#pragma unroll
        for (int r = 0; r < 8; r++)
#pragma unroll
            for (int c = 0; c < CU; c++)
                acc[r][c] = fma2(xv[r], wv[c], acc[r][c]);
    }

#pragma unroll
    for (int r = 0; r < 8; r++) {
        ulonglong2* op = (ulonglong2*)(out + (size_t)(base + r0 + r) * DOUT + c0);
#pragma unroll
        for (int c = 0; c < CU / 2; c++)
            op[c] = make_ulonglong2(acc[r][2 * c], acc[r][2 * c + 1]);
    }
}

// Single-matrix variant with row base (layer-1; 3 launches keep knn at idx3).
template<int FIN, int DOUT>
__global__ void __launch_bounds__(256) gemm1_kernel(
    const float* __restrict__ x,
    const float* __restrict__ W, const float* __restrict__ bias,
    float* __restrict__ out, int rowbase)
{
    constexpr int CT  = DOUT / 16;
    constexpr int CU  = CT / 2;
    constexpr int CPT = (CT / 4 > 0) ? CT / 4 : 1;
    constexpr int RXf = 132;

    __shared__ float xs[FIN * RXf];
    __shared__ float ws[FIN * DOUT];
    __shared__ float sb[DOUT];

    int tid  = threadIdx.x;
    int base = rowbase + blockIdx.x * 128;

    for (int i = tid; i < FIN * DOUT; i += 256) {
        int k = i / DOUT, c = i - k * DOUT;
        int q = c >> 2;
        int phys = (q % CPT) * 16 + (q / CPT);
        ws[k * DOUT + phys * 4 + (c & 3)] = W[i];
    }
    if (tid < DOUT) sb[tid] = bias[tid];
    for (int i = tid; i < 128 * FIN; i += 256) {
        int r = i / FIN, k = i - r * FIN;
        xs[k * RXf + r] = x[(size_t)(base + r) * FIN + k];
    }
    __syncthreads();

    int tx = tid & 15, ty = tid >> 4;
    int r0 = ty * 8, c0 = tx * CT;

    ull acc[8][CU];
    {
        const ull* bp = (const ull*)(sb + c0);
#pragma unroll
        for (int r = 0; r < 8; r++)
#pragma unroll
            for (int c = 0; c < CU; c++) acc[r][c] = bp[c];
    }

#pragma unroll 4
    for (int k = 0; k < FIN; k++) {
        const float4* xp = (const float4*)(xs + k * RXf + r0);
        float4 xa = xp[0], xb = xp[1];
        ull xv[8];
        xv[0] = bcast2(xa.x); xv[1] = bcast2(xa.y);
        xv[2] = bcast2(xa.z); xv[3] = bcast2(xa.w);
        xv[4] = bcast2(xb.x); xv[5] = bcast2(xb.y);
        xv[6] = bcast2(xb.z); xv[7] = bcast2(xb.w);

        ull wv[CU];
#pragma unroll
        for (int j = 0; j < CPT; j++) {
            ulonglong2 t = *(const ulonglong2*)(ws + k * DOUT + (j * 16 + tx) * 4);
            wv[2 * j] = t.x; wv[2 * j + 1] = t.y;
        }
#pragma unroll
        for (int r = 0; r < 8; r++)
#pragma unroll
            for (int c = 0; c < CU; c++)
                acc[r][c] = fma2(xv[r], wv[c], acc[r][c]);
    }

#pragma unroll
    for (int r = 0; r < 8; r++) {
        ulonglong2* op = (ulonglong2*)(out + (size_t)(base + r0 + r) * DOUT + c0);
#pragma unroll
        for (int c = 0; c < CU / 2; c++)
            op[c] = make_ulonglong2(acc[r][2 * c], acc[r][2 * c + 1]);
    }
}

// ---------------------------------------------------------------------------
// GATv2 attention + aggregation for layer 1, one warp per node.
// ---------------------------------------------------------------------------
__global__ void attn1_kernel(const float* __restrict__ xl, const float* __restrict__ xr,
                             const float* __restrict__ att, const float* __restrict__ bias,
                             float* __restrict__ out)
{
    constexpr int DOUT = D1, V = 2;
    int node = (blockIdx.x * blockDim.x + threadIdx.x) >> 5;
    int lane = threadIdx.x & 31;
    int b = node >> 10;
    const int* nidx = g_idx + (size_t)node * KK;
    int4 i0 = *(const int4*)nidx;
    int4 i1 = *(const int4*)(nidx + 4);
    int srcs[KK] = {i0.x, i0.y, i0.z, i0.w, i1.x, i1.y, i1.z, i1.w};

    int c0 = lane * V;

    float2 tr = *(const float2*)(xr + (size_t)node * DOUT + c0);
    float xrv[V] = {tr.x, tr.y};
    float2 ta = *(const float2*)(att + c0);
    float attv[V] = {ta.x, ta.y};

    float xnb[KK][V];
    float lg[KK];
#pragma unroll
    for (int k = 0; k < KK; k++) {
        int src = (b << 10) + srcs[k];
        float2 t = *(const float2*)(xl + (size_t)src * DOUT + c0);
        xnb[k][0] = t.x; xnb[k][1] = t.y;
        float s = 0.f;
#pragma unroll
        for (int v = 0; v < V; v++) {
            float e = xnb[k][v] + xrv[v];
            e = e > 0.f ? e : 0.2f * e;       // leaky_relu(0.2)
            s = fmaf(e, attv[v], s);
        }
        s += __shfl_xor_sync(0xffffffffu, s, 1);
        s += __shfl_xor_sync(0xffffffffu, s, 2);
        s += __shfl_xor_sync(0xffffffffu, s, 4);
        lg[k] = s;
    }

    float mx = lg[0];
#pragma unroll
    for (int k = 1; k < KK; k++) mx = fmaxf(mx, lg[k]);
    float ssum = 0.f;
#pragma unroll
    for (int k = 0; k < KK; k++) { lg[k] = __expf(lg[k] - mx); ssum += lg[k]; }
    float inv = 1.f / ssum;

    float o[V] = {0.f, 0.f};
#pragma unroll
    for (int k = 0; k < KK; k++) {
        float a = lg[k] * inv;
#pragma unroll
        for (int v = 0; v < V; v++) o[v] = fmaf(a, xnb[k][v], o[v]);
    }

    float2 bv = *(const float2*)(bias + c0);
    float2 r;
    r.x = fmaxf(o[0] + bv.x, 0.f);
    r.y = fmaxf(o[1] + bv.y, 0.f);
    *(float2*)(out + (size_t)node * DOUT + c0) = r;
}

// ---------------------------------------------------------------------------
// Layer-2 attention FUSED with partial mean-pool. 8 warps = 8 nodes/block;
// block partial (128 floats) to g_part.
// ---------------------------------------------------------------------------
__global__ void __launch_bounds__(256) attn2_pool_kernel(
    const float* __restrict__ xl, const float* __restrict__ xr,
    const float* __restrict__ att, const float* __restrict__ bias,
    float* __restrict__ part)
{
    constexpr int DOUT = D2, V = 4;
    __shared__ float sacc[8 * D2];

    int warp = threadIdx.x >> 5;
    int lane = threadIdx.x & 31;
    int node = blockIdx.x * 8 + warp;
    int b = node >> 10;
    const int* nidx = g_idx + (size_t)node * KK;
    int4 i0 = *(const int4*)nidx;
    int4 i1 = *(const int4*)(nidx + 4);
    int srcs[KK] = {i0.x, i0.y, i0.z, i0.w, i1.x, i1.y, i1.z, i1.w};

    int c0 = lane * V;

    float4 tr = *(const float4*)(xr + (size_t)node * DOUT + c0);
    float xrv[V] = {tr.x, tr.y, tr.z, tr.w};
    float4 ta = *(const float4*)(att + c0);
    float attv[V] = {ta.x, ta.y, ta.z, ta.w};

    float xnb[KK][V];
    float lg[KK];
#pragma unroll
    for (int k = 0; k < KK; k++) {
        int src = (b << 10) + srcs[k];
        float4 t = *(const float4*)(xl + (size_t)src * DOUT + c0);
        xnb[k][0] = t.x; xnb[k][1] = t.y; xnb[k][2] = t.z; xnb[k][3] = t.w;
        float s = 0.f;
#pragma unroll
        for (int v = 0; v < V; v++) {
            float e = xnb[k][v] + xrv[v];
            e = e > 0.f ? e : 0.2f * e;       // leaky_relu(0.2)
            s = fmaf(e, attv[v], s);
        }
        s += __shfl_xor_sync(0xffffffffu, s, 1);
        s += __shfl_xor_sync(0xffffffffu, s, 2);
        s += __shfl_xor_sync(0xffffffffu, s, 4);
        lg[k] = s;
    }

    float mx = lg[0];
#pragma unroll
    for (int k = 1; k < KK; k++) mx = fmaxf(mx, lg[k]);
    float ssum = 0.f;
#pragma unroll
    for (int k = 0; k < KK; k++) { lg[k] = __expf(lg[k] - mx); ssum += lg[k]; }
    float inv = 1.f / ssum;

    float o[V] = {0.f, 0.f, 0.f, 0.f};
#pragma unroll
    for (int k = 0; k < KK; k++) {
        float a = lg[k] * inv;
#pragma unroll
        for (int v = 0; v < V; v++) o[v] = fmaf(a, xnb[k][v], o[v]);
    }

    float4 bv = *(const float4*)(bias + c0);
    float4 r;
    r.x = fmaxf(o[0] + bv.x, 0.f);
    r.y = fmaxf(o[1] + bv.y, 0.f);
    r.z = fmaxf(o[2] + bv.z, 0.f);
    r.w = fmaxf(o[3] + bv.w, 0.f);
    *(float4*)(sacc + warp * D2 + c0) = r;
    __syncthreads();

    int t = threadIdx.x;
    if (t < D2) {
        float s = 0.f;
#pragma unroll
        for (int w = 0; w < 8; w++) s += sacc[w * D2 + t];
        part[(size_t)blockIdx.x * D2 + t] = s;
    }
}

// ---------------------------------------------------------------------------
// Final pool reduce: out[b][c] = (1/N) * sum over 128 block-partials.
// ---------------------------------------------------------------------------
__global__ void pool_reduce_kernel(const float* __restrict__ part,
                                   float* __restrict__ out)
{
    int b = blockIdx.x, t = threadIdx.x;  // 128 threads
    const float* p = part + (size_t)b * (NN / 8) * D2 + t;
    float s = 0.f;
#pragma unroll 8
    for (int j = 0; j < NN / 8; j++) s += p[(size_t)j * D2];
    out[b * D2 + t] = s * (1.f / (float)NN);
}

// ---------------------------------------------------------------------------
extern "C" void kernel_launch(void* const* d_in, const int* in_sizes, int n_in,
                              void* d_out, int out_size)
{
    const float* x     = (const float*)d_in[0];
    const float* pos   = (const float*)d_in[1];
    const float* Wl1   = (const float*)d_in[2];
    const float* bl1   = (const float*)d_in[3];
    const float* Wr1   = (const float*)d_in[4];
    const float* br1   = (const float*)d_in[5];
    const float* att1  = (const float*)d_in[6];
    const float* bias1 = (const float*)d_in[7];
    const float* Wl2   = (const float*)d_in[8];
    const float* bl2   = (const float*)d_in[9];
    const float* Wr2   = (const float*)d_in[10];
    const float* br2   = (const float*)d_in[11];
    const float* att2  = (const float*)d_in[12];
    const float* bias2 = (const float*)d_in[13];
    float* out = (float*)d_out;

    float *xl1, *xr1, *h1, *xl2, *xr2, *part;
    cudaGetSymbolAddress((void**)&xl1,  g_xl1);
    cudaGetSymbolAddress((void**)&xr1,  g_xr1);
    cudaGetSymbolAddress((void**)&h1,   g_h1);
    cudaGetSymbolAddress((void**)&xl2,  g_xl2);
    cudaGetSymbolAddress((void**)&xr2,  g_xr2);
    cudaGetSymbolAddress((void**)&part, g_part);

    // idx0-2: layer-1 transforms (Wl split in two so knn lands at idx3)
    gemm1_kernel<F1, D1><<<256, 256>>>(x, Wl1, bl1, xl1, 0);
    gemm1_kernel<F1, D1><<<256, 256>>>(x, Wl1, bl1, xl1, 32768);
    gemm1_kernel<F1, D1><<<512, 256>>>(x, Wr1, br1, xr1, 0);
    // idx3: KNN graph (PROFILED) — pair-min threshold, 2 threads/node
    knn_kernel<<<dim3(8, BB), 256>>>(pos);
    // idx4: layer-1 attention + ReLU
    attn1_kernel<<<(BB * NN * 32) / 256, 256>>>(xl1, xr1, att1, bias1, h1);
    // idx5: layer-2 transforms (combined grid.y picks Wl/Wr — R7 config)
    gemm2_kernel<D1, D2><<<dim3(BB * NN / 128, 2), 256>>>(
        h1, Wl2, bl2, Wr2, br2, xl2, xr2);
    // idx6: layer-2 attention + ReLU fused with partial mean pool
    attn2_pool_kernel<<<BB * NN / 8, 256>>>(xl2, xr2, att2, bias2, part);
    // idx7: final pool reduction
    pool_reduce_kernel<<<BB, 128>>>(part, out);
}

// round 16
// speedup vs baseline: 1.4136x; 1.0227x over previous
#include <cuda_runtime.h>
#include <cfloat>

#define BB 64
#define NN 1024
#define KK 8     // 7 knn + self
#define F1 16
#define D1 64    // H1*C1 = 4*16
#define D2 128   // H2*C2 = 4*32

typedef unsigned long long ull;
typedef unsigned int u32;

// Scratch (allocation-free rule: __device__ globals)
__device__ float g_xl1[BB * NN * D1];
__device__ float g_xr1[BB * NN * D1];
__device__ float g_h1 [BB * NN * D1];
__device__ float g_xl2[BB * NN * D2];
__device__ float g_xr2[BB * NN * D2];
__device__ float g_part[BB * (NN / 8) * D2];   // attn2+pool partials (4MB)
__device__ int   g_idx[BB * NN * KK];

// Packed dual-fp32 ops (sm_103a f32x2 pipe — ptxas never emits from C++)
__device__ __forceinline__ ull fma2(ull a, ull b, ull c) {
    ull d;
    asm("fma.rn.f32x2 %0, %1, %2, %3;" : "=l"(d) : "l"(a), "l"(b), "l"(c));
    return d;
}
__device__ __forceinline__ ull add2(ull a, ull b) {
    ull d;
    asm("add.rn.f32x2 %0, %1, %2;" : "=l"(d) : "l"(a), "l"(b));
    return d;
}
__device__ __forceinline__ ull bcast2(float v) {
    ull d;
    asm("mov.b64 %0, {%1, %1};" : "=l"(d) : "r"(__float_as_uint(v)));
    return d;
}
__device__ __forceinline__ float lo32(ull v) { return __uint_as_float((u32)v); }
__device__ __forceinline__ float hi32(ull v) { return __uint_as_float((u32)(v >> 32)); }

// Quarter stride in floats: 128 pairs * 8 + 8 pad = 1032 -> byte delta 4128
// -> bank shift 8 between quarter-groups in a warp: conflict-free LDS.128
// (R12 lesson: stride 4096 aliases all quarters to the same banks).
#define QSTRIDE 1032

// ---------------------------------------------------------------------------
// Branchless merge of partner lane's sorted 7-list (distance only).
// ---------------------------------------------------------------------------
__device__ __forceinline__ void merge7f(float lst[7], int delta)
{
    float ol[7];
#pragma unroll
    for (int j = 0; j < 7; j++) ol[j] = __shfl_xor_sync(0xffffffffu, lst[j], delta);
#pragma unroll
    for (int k = 0; k < 7; k++) {
        float x = ol[k];
#pragma unroll
        for (int j = 0; j < 7; j++) {
            float l = fminf(lst[j], x); x = fmaxf(lst[j], x); lst[j] = l;
        }
    }
}

// ---------------------------------------------------------------------------
// KNN, pair-min threshold + 4 threads/node. Thread (node, q) scans pair-
// quarter [q*128,(q+1)*128) (bank-skewed at QSTRIDE).
// Phase 1 (branchless): bubble pair-min through a sorted 7-list (14 FMNMX /
//   pair); two cross-lane merges -> t = global 7th-smallest pair-min.
//   EXACT bound: at most 6 elements lie strictly below d7, so at most 6
//   pair-mins < d7 => t >= d7 => the d<=t filter catches every top-7 element;
//   and only 7 pairs have pair-min <= t (sans ties) => <=14 collected total.
// Phase 2: recompute (bit-identical), collect indices with d <= t in index
//   order (16 slots/quarter).
// Final: q==0 lane runs exact stable top-7 (strict-< insert, index order).
// Block = 256 threads = 64 nodes; grid = (16, 64 batches) = 1024 blocks.
// ---------------------------------------------------------------------------
__global__ void knn_kernel(const float* __restrict__ pos)
{
    __shared__ __align__(16) float spp[4 * QSTRIDE];   // ~16.5KB
    __shared__ int sidx[64 * 64];                      // 16KB (16 slots/qtr)

    int b = blockIdx.y;
    const float* p = pos + (size_t)b * NN * 3;
    for (int i = threadIdx.x; i < NN; i += 256) {
        float x = p[i * 3 + 0], y = p[i * 3 + 1], z = p[i * 3 + 2];
        float w = x * x + y * y + z * z;
        int pair = i >> 1;
        float* dst = spp + (pair >> 7) * QSTRIDE + (pair & 127) * 8 + (i & 1);
        dst[0] = x; dst[2] = y; dst[4] = z; dst[6] = w;
    }
    __syncthreads();

    int tid = threadIdx.x;
    int q   = tid & 3;                  // pair-quarter 0..3
    int nl  = tid >> 2;                 // node local 0..63
    int n   = blockIdx.x * 64 + nl;     // node 0..1023

    int pn = n >> 1;
    const float* meq = spp + (pn >> 7) * QSTRIDE + (pn & 127) * 8 + (n & 1);
    float mex = meq[0], mey = meq[2], mez = meq[4], mew = meq[6];
    float cxs = -2.f * mex, cys = -2.f * mey, czs = -2.f * mez;
    ull cx = bcast2(cxs), cy = bcast2(cys), cz = bcast2(czs), cw = bcast2(mew);

    bool nEven = (n & 1) == 0;

    float lst[7];
#pragma unroll
    for (int j = 0; j < 7; j++) lst[j] = FLT_MAX;

    const ulonglong2* pp = (const ulonglong2*)(spp + q * QSTRIDE);
    int pbase = q * 128;

    // ---- Phase 1: branchless pair-min top-7 (per quarter) ----
#pragma unroll 2
    for (int i = 0; i < 128; i++) {
        ulonglong2 a  = pp[2 * i];      // {x0x1, y0y1}
        ulonglong2 c2 = pp[2 * i + 1];  // {z0z1, w0w1}
        ull d2 = add2(c2.y, cw);
        d2 = fma2(cx, a.x, d2);
        d2 = fma2(cy, a.y, d2);
        d2 = fma2(cz, c2.x, d2);
        float d0 = lo32(d2), d1 = hi32(d2);
        float pm = fminf(d0, d1);
        if (pbase + i == pn) pm = nEven ? d1 : d0;   // exclude self from min
#pragma unroll
        for (int j = 0; j < 7; j++) {
            float l = fminf(lst[j], pm); pm = fmaxf(lst[j], pm); lst[j] = l;
        }
    }
    // Merge the 4 quarter lists (lanes 4k..4k+3); all lanes get the result.
    merge7f(lst, 1);
    merge7f(lst, 2);
    float t = lst[6];   // global 7th-smallest pair-min >= d7 (exact bound)

    // ---- Phase 2: collect indices with d <= t (index order, per quarter) ----
    int cnt = 0;
    int sbase = q * 16;
#pragma unroll 2
    for (int i = 0; i < 128; i++) {
        ulonglong2 a  = pp[2 * i];
        ulonglong2 c2 = pp[2 * i + 1];
        ull d2 = add2(c2.y, cw);
        d2 = fma2(cx, a.x, d2);
        d2 = fma2(cy, a.y, d2);
        d2 = fma2(cz, c2.x, d2);
        float d0 = lo32(d2), d1 = hi32(d2);
        if (pbase + i == pn) { if (nEven) d0 = FLT_MAX; else d1 = FLT_MAX; }
        if (d0 <= t && cnt < 16) { sidx[(sbase + cnt) * 64 + nl] = (pbase + i) * 2;     cnt++; }
        if (d1 <= t && cnt < 16) { sidx[(sbase + cnt) * 64 + nl] = (pbase + i) * 2 + 1; cnt++; }
    }

    int lane = tid & 31;
    int base4 = lane & ~3;
    int c0q = __shfl_sync(0xffffffffu, cnt, base4 + 0);
    int c1q = __shfl_sync(0xffffffffu, cnt, base4 + 1);
    int c2q = __shfl_sync(0xffffffffu, cnt, base4 + 2);
    int c3q = __shfl_sync(0xffffffffu, cnt, base4 + 3);
    __syncwarp();

    // ---- Final: exact stable top-7 over collected candidates (q == 0) ----
    if (q == 0) {
        int cq[4] = {c0q, c1q, c2q, c3q};
        float bd[7]; int bi[7];
#pragma unroll
        for (int j = 0; j < 7; j++) { bd[j] = FLT_MAX; bi[j] = 0; }
#pragma unroll 1
        for (int qq = 0; qq < 4; qq++) {
#pragma unroll 1
            for (int jj = 0; jj < cq[qq]; jj++) {
                int idx = sidx[(qq * 16 + jj) * 64 + nl];
                int prr = idx >> 1;
                const float* qp = spp + (prr >> 7) * QSTRIDE + (prr & 127) * 8 + (idx & 1);
                float d = qp[6] + mew;          // bit-identical recompute
                d = fmaf(cxs, qp[0], d);
                d = fmaf(cys, qp[2], d);
                d = fmaf(czs, qp[4], d);
                if (d < bd[6]) {
                    bd[6] = d; bi[6] = idx;
#pragma unroll
                    for (int j = 6; j > 0; j--) {
                        if (bd[j] < bd[j - 1]) {   // strict: ties keep earlier idx
                            float td = bd[j]; bd[j] = bd[j - 1]; bd[j - 1] = td;
                            int   ti = bi[j]; bi[j] = bi[j - 1]; bi[j - 1] = ti;
                        }
                    }
                }
            }
        }
        int* o = g_idx + ((size_t)((b << 10) + n)) * KK;
#pragma unroll
        for (int j = 0; j < 7; j++) o[j] = bi[j];
        o[7] = n;  // self loop appended last, like the reference
    }
}

// ---------------------------------------------------------------------------
// Register-blocked GEMM (exact R7 body), combined Wl/Wr via grid.y.
// ---------------------------------------------------------------------------
template<int FIN, int DOUT>
__global__ void __launch_bounds__(256) gemm2_kernel(
    const float* __restrict__ x,
    const float* __restrict__ Wa, const float* __restrict__ ba,
    const float* __restrict__ Wb, const float* __restrict__ bb,
    float* __restrict__ outa, float* __restrict__ outb)
{
    constexpr int CT  = DOUT / 16;
    constexpr int CU  = CT / 2;
    constexpr int CPT = (CT / 4 > 0) ? CT / 4 : 1;
    constexpr int RXf = 132;

    __shared__ float xs[FIN * RXf];
    __shared__ float ws[FIN * DOUT];
    __shared__ float sb[DOUT];

    const float* W    = blockIdx.y ? Wb   : Wa;
    const float* bias = blockIdx.y ? bb   : ba;
    float*       out  = blockIdx.y ? outb : outa;

    int tid  = threadIdx.x;
    int base = blockIdx.x * 128;

    for (int i = tid; i < FIN * DOUT; i += 256) {
        int k = i / DOUT, c = i - k * DOUT;
        int q = c >> 2;
        int phys = (q % CPT) * 16 + (q / CPT);
        ws[k * DOUT + phys * 4 + (c & 3)] = W[i];
    }
    if (tid < DOUT) sb[tid] = bias[tid];
    for (int i = tid; i < 128 * FIN; i += 256) {
        int r = i / FIN, k = i - r * FIN;
        xs[k * RXf + r] = x[(size_t)(base + r) * FIN + k];
    }
    __syncthreads();

    int tx = tid & 15, ty = tid >> 4;
    int r0 = ty * 8, c0 = tx * CT;

    ull acc[8][CU];
    {
        const ull* bp = (const ull*)(sb + c0);
#pragma unroll
        for (int r = 0; r < 8; r++)
#pragma unroll
            for (int c = 0; c < CU; c++) acc[r][c] = bp[c];
    }

#pragma unroll 4
    for (int k = 0; k < FIN; k++) {
        const float4* xp = (const float4*)(xs + k * RXf + r0);
        float4 xa = xp[0], xb = xp[1];
        ull xv[8];
        xv[0] = bcast2(xa.x); xv[1] = bcast2(xa.y);
        xv[2] = bcast2(xa.z); xv[3] = bcast2(xa.w);
        xv[4] = bcast2(xb.x); xv[5] = bcast2(xb.y);
        xv[6] = bcast2(xb.z); xv[7] = bcast2(xb.w);

        ull wv[CU];
#pragma unroll
        for (int j = 0; j < CPT; j++) {
            ulonglong2 t = *(const ulonglong2*)(ws + k * DOUT + (j * 16 + tx) * 4);
            wv[2 * j] = t.x; wv[2 * j + 1] = t.y;
        }
#pragma unroll
        for (int r = 0; r < 8; r++)
#pragma unroll
            for (int c = 0; c < CU; c++)
                acc[r][c] = fma2(xv[r], wv[c], acc[r][c]);
    }

#pragma unroll
    for (int r = 0; r < 8; r++) {
        ulonglong2* op = (ulonglong2*)(out + (size_t)(base + r0 + r) * DOUT + c0);
#pragma unroll
        for (int c = 0; c < CU / 2; c++)
            op[c] = make_ulonglong2(acc[r][2 * c], acc[r][2 * c + 1]);
    }
}

// Single-matrix variant with row base (layer-1; 3 launches keep knn at idx3).
template<int FIN, int DOUT>
__global__ void __launch_bounds__(256) gemm1_kernel(
    const float* __restrict__ x,
    const float* __restrict__ W, const float* __restrict__ bias,
    float* __restrict__ out, int rowbase)
{
    constexpr int CT  = DOUT / 16;
    constexpr int CU  = CT / 2;
    constexpr int CPT = (CT / 4 > 0) ? CT / 4 : 1;
    constexpr int RXf = 132;

    __shared__ float xs[FIN * RXf];
    __shared__ float ws[FIN * DOUT];
    __shared__ float sb[DOUT];

    int tid  = threadIdx.x;
    int base = rowbase + blockIdx.x * 128;

    for (int i = tid; i < FIN * DOUT; i += 256) {
        int k = i / DOUT, c = i - k * DOUT;
        int q = c >> 2;
        int phys = (q % CPT) * 16 + (q / CPT);
        ws[k * DOUT + phys * 4 + (c & 3)] = W[i];
    }
    if (tid < DOUT) sb[tid] = bias[tid];
    for (int i = tid; i < 128 * FIN; i += 256) {
        int r = i / FIN, k = i - r * FIN;
        xs[k * RXf + r] = x[(size_t)(base + r) * FIN + k];
    }
    __syncthreads();

    int tx = tid & 15, ty = tid >> 4;
    int r0 = ty * 8, c0 = tx * CT;

    ull acc[8][CU];
    {
        const ull* bp = (const ull*)(sb + c0);
#pragma unroll
        for (int r = 0; r < 8; r++)
#pragma unroll
            for (int c = 0; c < CU; c++) acc[r][c] = bp[c];
    }

#pragma unroll 4
    for (int k = 0; k < FIN; k++) {
        const float4* xp = (const float4*)(xs + k * RXf + r0);
        float4 xa = xp[0], xb = xp[1];
        ull xv[8];
        xv[0] = bcast2(xa.x); xv[1] = bcast2(xa.y);
        xv[2] = bcast2(xa.z); xv[3] = bcast2(xa.w);
        xv[4] = bcast2(xb.x); xv[5] = bcast2(xb.y);
        xv[6] = bcast2(xb.z); xv[7] = bcast2(xb.w);

        ull wv[CU];
#pragma unroll
        for (int j = 0; j < CPT; j++) {
            ulonglong2 t = *(const ulonglong2*)(ws + k * DOUT + (j * 16 + tx) * 4);
            wv[2 * j] = t.x; wv[2 * j + 1] = t.y;
        }
#pragma unroll
        for (int r = 0; r < 8; r++)
#pragma unroll
            for (int c = 0; c < CU; c++)
                acc[r][c] = fma2(xv[r], wv[c], acc[r][c]);
    }

#pragma unroll
    for (int r = 0; r < 8; r++) {
        ulonglong2* op = (ulonglong2*)(out + (size_t)(base + r0 + r) * DOUT + c0);
#pragma unroll
        for (int c = 0; c < CU / 2; c++)
            op[c] = make_ulonglong2(acc[r][2 * c], acc[r][2 * c + 1]);
    }
}

// ---------------------------------------------------------------------------
// GATv2 attention + aggregation for layer 1, one warp per node.
// ---------------------------------------------------------------------------
__global__ void attn1_kernel(const float* __restrict__ xl, const float* __restrict__ xr,
                             const float* __restrict__ att, const float* __restrict__ bias,
                             float* __restrict__ out)
{
    constexpr int DOUT = D1, V = 2;
    int node = (blockIdx.x * blockDim.x + threadIdx.x) >> 5;
    int lane = threadIdx.x & 31;
    int b = node >> 10;
    const int* nidx = g_idx + (size_t)node * KK;
    int4 i0 = *(const int4*)nidx;
    int4 i1 = *(const int4*)(nidx + 4);
    int srcs[KK] = {i0.x, i0.y, i0.z, i0.w, i1.x, i1.y, i1.z, i1.w};

    int c0 = lane * V;

    float2 tr = *(const float2*)(xr + (size_t)node * DOUT + c0);
    float xrv[V] = {tr.x, tr.y};
    float2 ta = *(const float2*)(att + c0);
    float attv[V] = {ta.x, ta.y};

    float xnb[KK][V];
    float lg[KK];
#pragma unroll
    for (int k = 0; k < KK; k++) {
        int src = (b << 10) + srcs[k];
        float2 t = *(const float2*)(xl + (size_t)src * DOUT + c0);
        xnb[k][0] = t.x; xnb[k][1] = t.y;
        float s = 0.f;
#pragma unroll
        for (int v = 0; v < V; v++) {
            float e = xnb[k][v] + xrv[v];
            e = e > 0.f ? e : 0.2f * e;       // leaky_relu(0.2)
            s = fmaf(e, attv[v], s);
        }
        s += __shfl_xor_sync(0xffffffffu, s, 1);
        s += __shfl_xor_sync(0xffffffffu, s, 2);
        s += __shfl_xor_sync(0xffffffffu, s, 4);
        lg[k] = s;
    }

    float mx = lg[0];
#pragma unroll
    for (int k = 1; k < KK; k++) mx = fmaxf(mx, lg[k]);
    float ssum = 0.f;
#pragma unroll
    for (int k = 0; k < KK; k++) { lg[k] = __expf(lg[k] - mx); ssum += lg[k]; }
    float inv = 1.f / ssum;

    float o[V] = {0.f, 0.f};
#pragma unroll
    for (int k = 0; k < KK; k++) {
        float a = lg[k] * inv;
#pragma unroll
        for (int v = 0; v < V; v++) o[v] = fmaf(a, xnb[k][v], o[v]);
    }

    float2 bv = *(const float2*)(bias + c0);
    float2 r;
    r.x = fmaxf(o[0] + bv.x, 0.f);
    r.y = fmaxf(o[1] + bv.y, 0.f);
    *(float2*)(out + (size_t)node * DOUT + c0) = r;
}

// ---------------------------------------------------------------------------
// Layer-2 attention FUSED with partial mean-pool. 8 warps = 8 nodes/block;
// block partial (128 floats) to g_part.
// ---------------------------------------------------------------------------
__global__ void __launch_bounds__(256) attn2_pool_kernel(
    const float* __restrict__ xl, const float* __restrict__ xr,
    const float* __restrict__ att, const float* __restrict__ bias,
    float* __restrict__ part)
{
    constexpr int DOUT = D2, V = 4;
    __shared__ float sacc[8 * D2];

    int warp = threadIdx.x >> 5;
    int lane = threadIdx.x & 31;
    int node = blockIdx.x * 8 + warp;
    int b = node >> 10;
    const int* nidx = g_idx + (size_t)node * KK;
    int4 i0 = *(const int4*)nidx;
    int4 i1 = *(const int4*)(nidx + 4);
    int srcs[KK] = {i0.x, i0.y, i0.z, i0.w, i1.x, i1.y, i1.z, i1.w};

    int c0 = lane * V;

    float4 tr = *(const float4*)(xr + (size_t)node * DOUT + c0);
    float xrv[V] = {tr.x, tr.y, tr.z, tr.w};
    float4 ta = *(const float4*)(att + c0);
    float attv[V] = {ta.x, ta.y, ta.z, ta.w};

    float xnb[KK][V];
    float lg[KK];
#pragma unroll
    for (int k = 0; k < KK; k++) {
        int src = (b << 10) + srcs[k];
        float4 t = *(const float4*)(xl + (size_t)src * DOUT + c0);
        xnb[k][0] = t.x; xnb[k][1] = t.y; xnb[k][2] = t.z; xnb[k][3] = t.w;
        float s = 0.f;
#pragma unroll
        for (int v = 0; v < V; v++) {
            float e = xnb[k][v] + xrv[v];
            e = e > 0.f ? e : 0.2f * e;       // leaky_relu(0.2)
            s = fmaf(e, attv[v], s);
        }
        s += __shfl_xor_sync(0xffffffffu, s, 1);
        s += __shfl_xor_sync(0xffffffffu, s, 2);
        s += __shfl_xor_sync(0xffffffffu, s, 4);
        lg[k] = s;
    }

    float mx = lg[0];
#pragma unroll
    for (int k = 1; k < KK; k++) mx = fmaxf(mx, lg[k]);
    float ssum = 0.f;
#pragma unroll
    for (int k = 0; k < KK; k++) { lg[k] = __expf(lg[k] - mx); ssum += lg[k]; }
    float inv = 1.f / ssum;

    float o[V] = {0.f, 0.f, 0.f, 0.f};
#pragma unroll
    for (int k = 0; k < KK; k++) {
        float a = lg[k] * inv;
#pragma unroll
        for (int v = 0; v < V; v++) o[v] = fmaf(a, xnb[k][v], o[v]);
    }

    float4 bv = *(const float4*)(bias + c0);
    float4 r;
    r.x = fmaxf(o[0] + bv.x, 0.f);
    r.y = fmaxf(o[1] + bv.y, 0.f);
    r.z = fmaxf(o[2] + bv.z, 0.f);
    r.w = fmaxf(o[3] + bv.w, 0.f);
    *(float4*)(sacc + warp * D2 + c0) = r;
    __syncthreads();

    int t = threadIdx.x;
    if (t < D2) {
        float s = 0.f;
#pragma unroll
        for (int w = 0; w < 8; w++) s += sacc[w * D2 + t];
        part[(size_t)blockIdx.x * D2 + t] = s;
    }
}

// ---------------------------------------------------------------------------
// Final pool reduce: out[b][c] = (1/N) * sum over 128 block-partials.
// ---------------------------------------------------------------------------
__global__ void pool_reduce_kernel(const float* __restrict__ part,
                                   float* __restrict__ out)
{
    int b = blockIdx.x, t = threadIdx.x;  // 128 threads
    const float* p = part + (size_t)b * (NN / 8) * D2 + t;
    float s = 0.f;
#pragma unroll 8
    for (int j = 0; j < NN / 8; j++) s += p[(size_t)j * D2];
    out[b * D2 + t] = s * (1.f / (float)NN);
}

// ---------------------------------------------------------------------------
extern "C" void kernel_launch(void* const* d_in, const int* in_sizes, int n_in,
                              void* d_out, int out_size)
{
    const float* x     = (const float*)d_in[0];
    const float* pos   = (const float*)d_in[1];
    const float* Wl1   = (const float*)d_in[2];
    const float* bl1   = (const float*)d_in[3];
    const float* Wr1   = (const float*)d_in[4];
    const float* br1   = (const float*)d_in[5];
    const float* att1  = (const float*)d_in[6];
    const float* bias1 = (const float*)d_in[7];
    const float* Wl2   = (const float*)d_in[8];
    const float* bl2   = (const float*)d_in[9];
    const float* Wr2   = (const float*)d_in[10];
    const float* br2   = (const float*)d_in[11];
    const float* att2  = (const float*)d_in[12];
    const float* bias2 = (const float*)d_in[13];
    float* out = (float*)d_out;

    float *xl1, *xr1, *h1, *xl2, *xr2, *part;
    cudaGetSymbolAddress((void**)&xl1,  g_xl1);
    cudaGetSymbolAddress((void**)&xr1,  g_xr1);
    cudaGetSymbolAddress((void**)&h1,   g_h1);
    cudaGetSymbolAddress((void**)&xl2,  g_xl2);
    cudaGetSymbolAddress((void**)&xr2,  g_xr2);
    cudaGetSymbolAddress((void**)&part, g_part);

    // idx0-2: layer-1 transforms (Wl split in two so knn lands at idx3)
    gemm1_kernel<F1, D1><<<256, 256>>>(x, Wl1, bl1, xl1, 0);
    gemm1_kernel<F1, D1><<<256, 256>>>(x, Wl1, bl1, xl1, 32768);
    gemm1_kernel<F1, D1><<<512, 256>>>(x, Wr1, br1, xr1, 0);
    // idx3: KNN graph (PROFILED) — pair-min threshold, 4 threads/node
    knn_kernel<<<dim3(16, BB), 256>>>(pos);
    // idx4: layer-1 attention + ReLU
    attn1_kernel<<<(BB * NN * 32) / 256, 256>>>(xl1, xr1, att1, bias1, h1);
    // idx5: layer-2 transforms (combined grid.y picks Wl/Wr — R7 config)
    gemm2_kernel<D1, D2><<<dim3(BB * NN / 128, 2), 256>>>(
        h1, Wl2, bl2, Wr2, br2, xl2, xr2);
    // idx6: layer-2 attention + ReLU fused with partial mean pool
    attn2_pool_kernel<<<BB * NN / 8, 256>>>(xl2, xr2, att2, bias2, part);
    // idx7: final pool reduction
    pool_reduce_kernel<<<BB, 128>>>(part, out);
}

// round 17
// speedup vs baseline: 1.4319x; 1.0129x over previous
#include <cuda_runtime.h>
#include <cfloat>

#define BB 64
#define NN 1024
#define KK 8     // 7 knn + self
#define F1 16
#define D1 64    // H1*C1 = 4*16
#define D2 128   // H2*C2 = 4*32

typedef unsigned long long ull;
typedef unsigned int u32;

// Scratch (allocation-free rule: __device__ globals)
__device__ float g_xl1[BB * NN * D1];
__device__ float g_xr1[BB * NN * D1];
__device__ float g_h1 [BB * NN * D1];
__device__ float g_xl2[BB * NN * D2];
__device__ float g_xr2[BB * NN * D2];
__device__ float g_part[BB * (NN / 8) * D2];   // attn2+pool partials (4MB)
__device__ int   g_idx[BB * NN * KK];

// Packed dual-fp32 ops (sm_103a f32x2 pipe — ptxas never emits from C++)
__device__ __forceinline__ ull fma2(ull a, ull b, ull c) {
    ull d;
    asm("fma.rn.f32x2 %0, %1, %2, %3;" : "=l"(d) : "l"(a), "l"(b), "l"(c));
    return d;
}
__device__ __forceinline__ ull add2(ull a, ull b) {
    ull d;
    asm("add.rn.f32x2 %0, %1, %2;" : "=l"(d) : "l"(a), "l"(b));
    return d;
}
__device__ __forceinline__ ull bcast2(float v) {
    ull d;
    asm("mov.b64 %0, {%1, %1};" : "=l"(d) : "r"(__float_as_uint(v)));
    return d;
}
__device__ __forceinline__ float lo32(ull v) { return __uint_as_float((u32)v); }
__device__ __forceinline__ float hi32(ull v) { return __uint_as_float((u32)(v >> 32)); }

// Quarter stride in floats: 128 pairs * 8 + 8 pad = 1032 -> byte delta 4128
// -> bank shift 8 between quarter-groups in a warp: conflict-free LDS.128
// (R12 lesson: stride 4096 aliases all quarters to the same banks).
#define QSTRIDE 1032
#define QSLOTS  28   // strict per-quarter bound: 7 hit quads x 4 elements

// ---------------------------------------------------------------------------
// Branchless merge of partner lane's sorted 7-list (distance only).
// ---------------------------------------------------------------------------
__device__ __forceinline__ void merge7f(float lst[7], int delta)
{
    float ol[7];
#pragma unroll
    for (int j = 0; j < 7; j++) ol[j] = __shfl_xor_sync(0xffffffffu, lst[j], delta);
#pragma unroll
    for (int k = 0; k < 7; k++) {
        float x = ol[k];
#pragma unroll
        for (int j = 0; j < 7; j++) {
            float l = fminf(lst[j], x); x = fmaxf(lst[j], x); lst[j] = l;
        }
    }
}

// ---------------------------------------------------------------------------
// KNN, QUAD-min threshold + 4 threads/node. Thread (node, q) scans 64 quads
// (256 candidates) in its bank-skewed quarter.
// Phase 1 (branchless): reduce each quad of 4 candidates to its min (3 FMNMX)
//   and bubble through a sorted 7-list (14 FMNMX per QUAD, was per pair).
//   Two cross-lane merges -> t = global 7th-smallest quad-min. EXACT bound:
//   at most 6 elements lie strictly below d7 => at most 6 quad-mins < d7
//   => t >= d7 => the d<=t filter catches every top-7 element. Elements <= t
//   come only from quads with quad-min <= t (~7) => <=28 collected (QSLOTS).
// Phase 2: recompute (bit-identical), collect indices with d <= t in index
//   order into per-quarter short slots.
// Final: q==0 lane runs exact stable top-7 (strict-< insert, index order).
// Block = 256 threads = 64 nodes; grid = (16, 64 batches) = 1024 blocks.
// ---------------------------------------------------------------------------
__global__ void knn_kernel(const float* __restrict__ pos)
{
    __shared__ __align__(16) float spp[4 * QSTRIDE];   // ~16.5KB
    __shared__ short sidx[4 * QSLOTS * 64];            // 14.3KB

    int b = blockIdx.y;
    const float* p = pos + (size_t)b * NN * 3;
    for (int i = threadIdx.x; i < NN; i += 256) {
        float x = p[i * 3 + 0], y = p[i * 3 + 1], z = p[i * 3 + 2];
        float w = x * x + y * y + z * z;
        int pair = i >> 1;
        float* dst = spp + (pair >> 7) * QSTRIDE + (pair & 127) * 8 + (i & 1);
        dst[0] = x; dst[2] = y; dst[4] = z; dst[6] = w;
    }
    __syncthreads();

    int tid = threadIdx.x;
    int q   = tid & 3;                  // quarter 0..3
    int nl  = tid >> 2;                 // node local 0..63
    int n   = blockIdx.x * 64 + nl;     // node 0..1023

    int pn = n >> 1;
    const float* meq = spp + (pn >> 7) * QSTRIDE + (pn & 127) * 8 + (n & 1);
    float mex = meq[0], mey = meq[2], mez = meq[4], mew = meq[6];
    float cxs = -2.f * mex, cys = -2.f * mey, czs = -2.f * mez;
    ull cx = bcast2(cxs), cy = bcast2(cys), cz = bcast2(czs), cw = bcast2(mew);

    int qn  = n >> 2;                   // global quad index containing self
    int sel = n & 3;                    // element-in-quad of self

    float lst[7];
#pragma unroll
    for (int j = 0; j < 7; j++) lst[j] = FLT_MAX;

    const ulonglong2* pp = (const ulonglong2*)(spp + q * QSTRIDE);
    int qbase = q * 64;                 // quad base of this quarter

    // ---- Phase 1: branchless quad-min top-7 ----
#pragma unroll 2
    for (int i = 0; i < 64; i++) {
        ulonglong2 a0 = pp[4 * i + 0];  // pair 2i:   {x0x1, y0y1}
        ulonglong2 b0 = pp[4 * i + 1];  //            {z0z1, w0w1}
        ulonglong2 a1 = pp[4 * i + 2];  // pair 2i+1
        ulonglong2 b1 = pp[4 * i + 3];
        ull dA = add2(b0.y, cw);
        dA = fma2(cx, a0.x, dA); dA = fma2(cy, a0.y, dA); dA = fma2(cz, b0.x, dA);
        ull dB = add2(b1.y, cw);
        dB = fma2(cx, a1.x, dB); dB = fma2(cy, a1.y, dB); dB = fma2(cz, b1.x, dB);
        float d0 = lo32(dA), d1 = hi32(dA), d2v = lo32(dB), d3v = hi32(dB);
        if (qbase + i == qn) {          // rare: exclude self from min
            if      (sel == 0) d0  = FLT_MAX;
            else if (sel == 1) d1  = FLT_MAX;
            else if (sel == 2) d2v = FLT_MAX;
            else               d3v = FLT_MAX;
        }
        float pm = fminf(fminf(d0, d1), fminf(d2v, d3v));
#pragma unroll
        for (int j = 0; j < 7; j++) {
            float l = fminf(lst[j], pm); pm = fmaxf(lst[j], pm); lst[j] = l;
        }
    }
    // Merge the 4 quarter lists (lanes 4k..4k+3); all lanes get the result.
    merge7f(lst, 1);
    merge7f(lst, 2);
    float t = lst[6];   // global 7th-smallest quad-min >= d7 (exact bound)

    // ---- Phase 2: collect indices with d <= t (index order, per quarter) ----
    int cnt = 0;
    int sbase = q * QSLOTS;
#pragma unroll 2
    for (int i = 0; i < 64; i++) {
        ulonglong2 a0 = pp[4 * i + 0];
        ulonglong2 b0 = pp[4 * i + 1];
        ulonglong2 a1 = pp[4 * i + 2];
        ulonglong2 b1 = pp[4 * i + 3];
        ull dA = add2(b0.y, cw);
        dA = fma2(cx, a0.x, dA); dA = fma2(cy, a0.y, dA); dA = fma2(cz, b0.x, dA);
        ull dB = add2(b1.y, cw);
        dB = fma2(cx, a1.x, dB); dB = fma2(cy, a1.y, dB); dB = fma2(cz, b1.x, dB);
        float d0 = lo32(dA), d1 = hi32(dA), d2v = lo32(dB), d3v = hi32(dB);
        if (qbase + i == qn) {
            if      (sel == 0) d0  = FLT_MAX;
            else if (sel == 1) d1  = FLT_MAX;
            else if (sel == 2) d2v = FLT_MAX;
            else               d3v = FLT_MAX;
        }
        int cb = (qbase + i) * 4;
        if (d0  <= t && cnt < QSLOTS) { sidx[(sbase + cnt) * 64 + nl] = (short)(cb);     cnt++; }
        if (d1  <= t && cnt < QSLOTS) { sidx[(sbase + cnt) * 64 + nl] = (short)(cb + 1); cnt++; }
        if (d2v <= t && cnt < QSLOTS) { sidx[(sbase + cnt) * 64 + nl] = (short)(cb + 2); cnt++; }
        if (d3v <= t && cnt < QSLOTS) { sidx[(sbase + cnt) * 64 + nl] = (short)(cb + 3); cnt++; }
    }

    int lane = tid & 31;
    int base4 = lane & ~3;
    int c0q = __shfl_sync(0xffffffffu, cnt, base4 + 0);
    int c1q = __shfl_sync(0xffffffffu, cnt, base4 + 1);
    int c2q = __shfl_sync(0xffffffffu, cnt, base4 + 2);
    int c3q = __shfl_sync(0xffffffffu, cnt, base4 + 3);
    __syncwarp();

    // ---- Final: exact stable top-7 over collected candidates (q == 0) ----
    if (q == 0) {
        int cq[4] = {c0q, c1q, c2q, c3q};
        float bd[7]; int bi[7];
#pragma unroll
        for (int j = 0; j < 7; j++) { bd[j] = FLT_MAX; bi[j] = 0; }
#pragma unroll 1
        for (int qq = 0; qq < 4; qq++) {
#pragma unroll 1
            for (int jj = 0; jj < cq[qq]; jj++) {
                int idx = sidx[(qq * QSLOTS + jj) * 64 + nl];
                int prr = idx >> 1;
                const float* qp = spp + (prr >> 7) * QSTRIDE + (prr & 127) * 8 + (idx & 1);
                float d = qp[6] + mew;          // bit-identical recompute
                d = fmaf(cxs, qp[0], d);
                d = fmaf(cys, qp[2], d);
                d = fmaf(czs, qp[4], d);
                if (d < bd[6]) {
                    bd[6] = d; bi[6] = idx;
#pragma unroll
                    for (int j = 6; j > 0; j--) {
                        if (bd[j] < bd[j - 1]) {   // strict: ties keep earlier idx
                            float td = bd[j]; bd[j] = bd[j - 1]; bd[j - 1] = td;
                            int   ti = bi[j]; bi[j] = bi[j - 1]; bi[j - 1] = ti;
                        }
                    }
                }
            }
        }
        int* o = g_idx + ((size_t)((b << 10) + n)) * KK;
#pragma unroll
        for (int j = 0; j < 7; j++) o[j] = bi[j];
        o[7] = n;  // self loop appended last, like the reference
    }
}

// ---------------------------------------------------------------------------
// Register-blocked GEMM (exact R7 body), combined Wl/Wr via grid.y.
// ---------------------------------------------------------------------------
template<int FIN, int DOUT>
__global__ void __launch_bounds__(256) gemm2_kernel(
    const float* __restrict__ x,
    const float* __restrict__ Wa, const float* __restrict__ ba,
    const float* __restrict__ Wb, const float* __restrict__ bb,
    float* __restrict__ outa, float* __restrict__ outb)
{
    constexpr int CT  = DOUT / 16;
    constexpr int CU  = CT / 2;
    constexpr int CPT = (CT / 4 > 0) ? CT / 4 : 1;
    constexpr int RXf = 132;

    __shared__ float xs[FIN * RXf];
    __shared__ float ws[FIN * DOUT];
    __shared__ float sb[DOUT];

    const float* W    = blockIdx.y ? Wb   : Wa;
    const float* bias = blockIdx.y ? bb   : ba;
    float*       out  = blockIdx.y ? outb : outa;

    int tid  = threadIdx.x;
    int base = blockIdx.x * 128;

    for (int i = tid; i < FIN * DOUT; i += 256) {
        int k = i / DOUT, c = i - k * DOUT;
        int q = c >> 2;
        int phys = (q % CPT) * 16 + (q / CPT);
        ws[k * DOUT + phys * 4 + (c & 3)] = W[i];
    }
    if (tid < DOUT) sb[tid] = bias[tid];
    for (int i = tid; i < 128 * FIN; i += 256) {
        int r = i / FIN, k = i - r * FIN;
        xs[k * RXf + r] = x[(size_t)(base + r) * FIN + k];
    }
    __syncthreads();

    int tx = tid & 15, ty = tid >> 4;
    int r0 = ty * 8, c0 = tx * CT;

    ull acc[8][CU];
    {
        const ull* bp = (const ull*)(sb + c0);
#pragma unroll
        for (int r = 0; r < 8; r++)
#pragma unroll
            for (int c = 0; c < CU; c++) acc[r][c] = bp[c];
    }

#pragma unroll 4
    for (int k = 0; k < FIN; k++) {
        const float4* xp = (const float4*)(xs + k * RXf + r0);
        float4 xa = xp[0], xb = xp[1];
        ull xv[8];
        xv[0] = bcast2(xa.x); xv[1] = bcast2(xa.y);
        xv[2] = bcast2(xa.z); xv[3] = bcast2(xa.w);
        xv[4] = bcast2(xb.x); xv[5] = bcast2(xb.y);
        xv[6] = bcast2(xb.z); xv[7] = bcast2(xb.w);

        ull wv[CU];
#pragma unroll
        for (int j = 0; j < CPT; j++) {
            ulonglong2 t = *(const ulonglong2*)(ws + k * DOUT + (j * 16 + tx) * 4);
            wv[2 * j] = t.x; wv[2 * j + 1] = t.y;
        }
#pragma unroll
        for (int r = 0; r < 8; r++)
#pragma unroll
            for (int c = 0; c < CU; c++)
                acc[r][c] = fma2(xv[r], wv[c], acc[r][c]);
    }

#pragma unroll
    for (int r = 0; r < 8; r++) {
        ulonglong2* op = (ulonglong2*)(out + (size_t)(base + r0 + r) * DOUT + c0);
#pragma unroll
        for (int c = 0; c < CU / 2; c++)
            op[c] = make_ulonglong2(acc[r][2 * c], acc[r][2 * c + 1]);
    }
}

// Single-matrix variant with row base (layer-1; 3 launches keep knn at idx3).
template<int FIN, int DOUT>
__global__ void __launch_bounds__(256) gemm1_kernel(
    const float* __restrict__ x,
    const float* __restrict__ W, const float* __restrict__ bias,
    float* __restrict__ out, int rowbase)
{
    constexpr int CT  = DOUT / 16;
    constexpr int CU  = CT / 2;
    constexpr int CPT = (CT / 4 > 0) ? CT / 4 : 1;
    constexpr int RXf = 132;

    __shared__ float xs[FIN * RXf];
    __shared__ float ws[FIN * DOUT];
    __shared__ float sb[DOUT];

    int tid  = threadIdx.x;
    int base = rowbase + blockIdx.x * 128;

    for (int i = tid; i < FIN * DOUT; i += 256) {
        int k = i / DOUT, c = i - k * DOUT;
        int q = c >> 2;
        int phys = (q % CPT) * 16 + (q / CPT);
        ws[k * DOUT + phys * 4 + (c & 3)] = W[i];
    }
    if (tid < DOUT) sb[tid] = bias[tid];
    for (int i = tid; i < 128 * FIN; i += 256) {
        int r = i / FIN, k = i - r * FIN;
        xs[k * RXf + r] = x[(size_t)(base + r) * FIN + k];
    }
    __syncthreads();

    int tx = tid & 15, ty = tid >> 4;
    int r0 = ty * 8, c0 = tx * CT;

    ull acc[8][CU];
    {
        const ull* bp = (const ull*)(sb + c0);
#pragma unroll
        for (int r = 0; r < 8; r++)
#pragma unroll
            for (int c = 0; c < CU; c++) acc[r][c] = bp[c];
    }

#pragma unroll 4
    for (int k = 0; k < FIN; k++) {
        const float4* xp = (const float4*)(xs + k * RXf + r0);
        float4 xa = xp[0], xb = xp[1];
        ull xv[8];
        xv[0] = bcast2(xa.x); xv[1] = bcast2(xa.y);
        xv[2] = bcast2(xa.z); xv[3] = bcast2(xa.w);
        xv[4] = bcast2(xb.x); xv[5] = bcast2(xb.y);
        xv[6] = bcast2(xb.z); xv[7] = bcast2(xb.w);

        ull wv[CU];
#pragma unroll
        for (int j = 0; j < CPT; j++) {
            ulonglong2 t = *(const ulonglong2*)(ws + k * DOUT + (j * 16 + tx) * 4);
            wv[2 * j] = t.x; wv[2 * j + 1] = t.y;
        }
#pragma unroll
        for (int r = 0; r < 8; r++)
#pragma unroll
            for (int c = 0; c < CU; c++)
                acc[r][c] = fma2(xv[r], wv[c], acc[r][c]);
    }

#pragma unroll
    for (int r = 0; r < 8; r++) {
        ulonglong2* op = (ulonglong2*)(out + (size_t)(base + r0 + r) * DOUT + c0);
#pragma unroll
        for (int c = 0; c < CU / 2; c++)
            op[c] = make_ulonglong2(acc[r][2 * c], acc[r][2 * c + 1]);
    }
}

// ---------------------------------------------------------------------------
// GATv2 attention + aggregation for layer 1, one warp per node.
// ---------------------------------------------------------------------------
__global__ void attn1_kernel(const float* __restrict__ xl, const float* __restrict__ xr,
                             const float* __restrict__ att, const float* __restrict__ bias,
                             float* __restrict__ out)
{
    constexpr int DOUT = D1, V = 2;
    int node = (blockIdx.x * blockDim.x + threadIdx.x) >> 5;
    int lane = threadIdx.x & 31;
    int b = node >> 10;
    const int* nidx = g_idx + (size_t)node * KK;
    int4 i0 = *(const int4*)nidx;
    int4 i1 = *(const int4*)(nidx + 4);
    int srcs[KK] = {i0.x, i0.y, i0.z, i0.w, i1.x, i1.y, i1.z, i1.w};

    int c0 = lane * V;

    float2 tr = *(const float2*)(xr + (size_t)node * DOUT + c0);
    float xrv[V] = {tr.x, tr.y};
    float2 ta = *(const float2*)(att + c0);
    float attv[V] = {ta.x, ta.y};

    float xnb[KK][V];
    float lg[KK];
#pragma unroll
    for (int k = 0; k < KK; k++) {
        int src = (b << 10) + srcs[k];
        float2 t = *(const float2*)(xl + (size_t)src * DOUT + c0);
        xnb[k][0] = t.x; xnb[k][1] = t.y;
        float s = 0.f;
#pragma unroll
        for (int v = 0; v < V; v++) {
            float e = xnb[k][v] + xrv[v];
            e = e > 0.f ? e : 0.2f * e;       // leaky_relu(0.2)
            s = fmaf(e, attv[v], s);
        }
        s += __shfl_xor_sync(0xffffffffu, s, 1);
        s += __shfl_xor_sync(0xffffffffu, s, 2);
        s += __shfl_xor_sync(0xffffffffu, s, 4);
        lg[k] = s;
    }

    float mx = lg[0];
#pragma unroll
    for (int k = 1; k < KK; k++) mx = fmaxf(mx, lg[k]);
    float ssum = 0.f;
#pragma unroll
    for (int k = 0; k < KK; k++) { lg[k] = __expf(lg[k] - mx); ssum += lg[k]; }
    float inv = 1.f / ssum;

    float o[V] = {0.f, 0.f};
#pragma unroll
    for (int k = 0; k < KK; k++) {
        float a = lg[k] * inv;
#pragma unroll
        for (int v = 0; v < V; v++) o[v] = fmaf(a, xnb[k][v], o[v]);
    }

    float2 bv = *(const float2*)(bias + c0);
    float2 r;
    r.x = fmaxf(o[0] + bv.x, 0.f);
    r.y = fmaxf(o[1] + bv.y, 0.f);
    *(float2*)(out + (size_t)node * DOUT + c0) = r;
}

// ---------------------------------------------------------------------------
// Layer-2 attention FUSED with partial mean-pool. 8 warps = 8 nodes/block;
// block partial (128 floats) to g_part.
// ---------------------------------------------------------------------------
__global__ void __launch_bounds__(256) attn2_pool_kernel(
    const float* __restrict__ xl, const float* __restrict__ xr,
    const float* __restrict__ att, const float* __restrict__ bias,
    float* __restrict__ part)
{
    constexpr int DOUT = D2, V = 4;
    __shared__ float sacc[8 * D2];

    int warp = threadIdx.x >> 5;
    int lane = threadIdx.x & 31;
    int node = blockIdx.x * 8 + warp;
    int b = node >> 10;
    const int* nidx = g_idx + (size_t)node * KK;
    int4 i0 = *(const int4*)nidx;
    int4 i1 = *(const int4*)(nidx + 4);
    int srcs[KK] = {i0.x, i0.y, i0.z, i0.w, i1.x, i1.y, i1.z, i1.w};

    int c0 = lane * V;

    float4 tr = *(const float4*)(xr + (size_t)node * DOUT + c0);
    float xrv[V] = {tr.x, tr.y, tr.z, tr.w};
    float4 ta = *(const float4*)(att + c0);
    float attv[V] = {ta.x, ta.y, ta.z, ta.w};

    float xnb[KK][V];
    float lg[KK];
#pragma unroll
    for (int k = 0; k < KK; k++) {
        int src = (b << 10) + srcs[k];
        float4 t = *(const float4*)(xl + (size_t)src * DOUT + c0);
        xnb[k][0] = t.x; xnb[k][1] = t.y; xnb[k][2] = t.z; xnb[k][3] = t.w;
        float s = 0.f;
#pragma unroll
        for (int v = 0; v < V; v++) {
            float e = xnb[k][v] + xrv[v];
            e = e > 0.f ? e : 0.2f * e;       // leaky_relu(0.2)
            s = fmaf(e, attv[v], s);
        }
        s += __shfl_xor_sync(0xffffffffu, s, 1);
        s += __shfl_xor_sync(0xffffffffu, s, 2);
        s += __shfl_xor_sync(0xffffffffu, s, 4);
        lg[k] = s;
    }

    float mx = lg[0];
#pragma unroll
    for (int k = 1; k < KK; k++) mx = fmaxf(mx, lg[k]);
    float ssum = 0.f;
#pragma unroll
    for (int k = 0; k < KK; k++) { lg[k] = __expf(lg[k] - mx); ssum += lg[k]; }
    float inv = 1.f / ssum;

    float o[V] = {0.f, 0.f, 0.f, 0.f};
#pragma unroll
    for (int k = 0; k < KK; k++) {
        float a = lg[k] * inv;
#pragma unroll
        for (int v = 0; v < V; v++) o[v] = fmaf(a, xnb[k][v], o[v]);
    }

    float4 bv = *(const float4*)(bias + c0);
    float4 r;
    r.x = fmaxf(o[0] + bv.x, 0.f);
    r.y = fmaxf(o[1] + bv.y, 0.f);
    r.z = fmaxf(o[2] + bv.z, 0.f);
    r.w = fmaxf(o[3] + bv.w, 0.f);
    *(float4*)(sacc + warp * D2 + c0) = r;
    __syncthreads();

    int t = threadIdx.x;
    if (t < D2) {
        float s = 0.f;
#pragma unroll
        for (int w = 0; w < 8; w++) s += sacc[w * D2 + t];
        part[(size_t)blockIdx.x * D2 + t] = s;
    }
}

// ---------------------------------------------------------------------------
// Final pool reduce: out[b][c] = (1/N) * sum over 128 block-partials.
// ---------------------------------------------------------------------------
__global__ void pool_reduce_kernel(const float* __restrict__ part,
                                   float* __restrict__ out)
{
    int b = blockIdx.x, t = threadIdx.x;  // 128 threads
    const float* p = part + (size_t)b * (NN / 8) * D2 + t;
    float s = 0.f;
#pragma unroll 8
    for (int j = 0; j < NN / 8; j++) s += p[(size_t)j * D2];
    out[b * D2 + t] = s * (1.f / (float)NN);
}

// ---------------------------------------------------------------------------
extern "C" void kernel_launch(void* const* d_in, const int* in_sizes, int n_in,
                              void* d_out, int out_size)
{
    const float* x     = (const float*)d_in[0];
    const float* pos   = (const float*)d_in[1];
    const float* Wl1   = (const float*)d_in[2];
    const float* bl1   = (const float*)d_in[3];
    const float* Wr1   = (const float*)d_in[4];
    const float* br1   = (const float*)d_in[5];
    const float* att1  = (const float*)d_in[6];
    const float* bias1 = (const float*)d_in[7];
    const float* Wl2   = (const float*)d_in[8];
    const float* bl2   = (const float*)d_in[9];
    const float* Wr2   = (const float*)d_in[10];
    const float* br2   = (const float*)d_in[11];
    const float* att2  = (const float*)d_in[12];
    const float* bias2 = (const float*)d_in[13];
    float* out = (float*)d_out;

    float *xl1, *xr1, *h1, *xl2, *xr2, *part;
    cudaGetSymbolAddress((void**)&xl1,  g_xl1);
    cudaGetSymbolAddress((void**)&xr1,  g_xr1);
    cudaGetSymbolAddress((void**)&h1,   g_h1);
    cudaGetSymbolAddress((void**)&xl2,  g_xl2);
    cudaGetSymbolAddress((void**)&xr2,  g_xr2);
    cudaGetSymbolAddress((void**)&part, g_part);

    // idx0-2: layer-1 transforms (Wl split in two so knn lands at idx3)
    gemm1_kernel<F1, D1><<<256, 256>>>(x, Wl1, bl1, xl1, 0);
    gemm1_kernel<F1, D1><<<256, 256>>>(x, Wl1, bl1, xl1, 32768);
    gemm1_kernel<F1, D1><<<512, 256>>>(x, Wr1, br1, xr1, 0);
    // idx3: KNN graph (PROFILED) — quad-min threshold, 4 threads/node
    knn_kernel<<<dim3(16, BB), 256>>>(pos);
    // idx4: layer-1 attention + ReLU
    attn1_kernel<<<(BB * NN * 32) / 256, 256>>>(xl1, xr1, att1, bias1, h1);
    // idx5: layer-2 transforms (combined grid.y picks Wl/Wr — R7 config)
    gemm2_kernel<D1, D2><<<dim3(BB * NN / 128, 2), 256>>>(
        h1, Wl2, bl2, Wr2, br2, xl2, xr2);
    // idx6: layer-2 attention + ReLU fused with partial mean pool
    attn2_pool_kernel<<<BB * NN / 8, 256>>>(xl2, xr2, att2, bias2, part);
    // idx7: final pool reduction
    pool_reduce_kernel<<<BB, 128>>>(part, out);
}